// round 13
// baseline (speedup 1.0000x reference)
#include <cuda_runtime.h>
#include <cuda_bf16.h>
#include <math.h>
#include <stdint.h>

#define N_NODES 50000
#define N_EDGES 800000
#define ET (N_EDGES + N_NODES)
#define D 128
#define BQ 1024
#define H3 384
#define EPSV 1e-5f
#define NT_TILES 391             // ceil(50000/128)
#define NB_SCAN 196              // ceil(50000/256)

#define NEG_INF (__int_as_float(0xff800000))

// ---------------- scratch (device globals; no allocation) ----------------
__device__ __nv_bfloat16 g_h16[(size_t)N_NODES * D];
__device__ float g_agg[N_NODES * D];
__device__ float g_hn[N_NODES * D];
__device__ float g_as[N_NODES];
__device__ float g_ad[N_NODES];
__device__ float g_e[ET];
__device__ float g_musum2[2 * D];
__device__ float g_varsum2[2 * D];
__device__ float g_z1[BQ * H3];
__device__ float g_lse[BQ];
__device__ float g_pmax[(size_t)BQ * NT_TILES];
__device__ float g_psum[(size_t)BQ * NT_TILES];
__device__ __nv_bfloat16 g_w16[(size_t)N_NODES * H3];
__device__ __nv_bfloat16 g_z16[BQ * H3];
// CSR
__device__ int g_deg[N_NODES];
__device__ int g_off[N_NODES + 1];
__device__ int g_cur[N_NODES];
__device__ int g_srcl[ET];
__device__ int g_bsum[NB_SCAN];
__device__ int g_boff[NB_SCAN];

// ================= CSR build =================
__global__ void k_zero_deg() {
    int i = blockIdx.x * blockDim.x + threadIdx.x;
    if (i < N_NODES) g_deg[i] = 0;
    if (i < 2 * D) { g_musum2[i] = 0.f; g_varsum2[i] = 0.f; }
}
__global__ void k_count(const int* __restrict__ ei) {
    int i = blockIdx.x * blockDim.x + threadIdx.x;
    if (i >= ET) return;
    int dst = (i < N_EDGES) ? ei[N_EDGES + i] : (i - N_EDGES);
    atomicAdd(&g_deg[dst], 1);
}
__global__ void k_bsums() {
    int tid = threadIdx.x;
    int i = blockIdx.x * 256 + tid;
    int v = (i < N_NODES) ? g_deg[i] : 0;
    int lane = tid & 31, wid = tid >> 5;
#pragma unroll
    for (int o = 16; o; o >>= 1) v += __shfl_down_sync(0xffffffff, v, o);
    __shared__ int ws[8];
    if (lane == 0) ws[wid] = v;
    __syncthreads();
    if (tid == 0) {
        int s = 0;
#pragma unroll
        for (int w = 0; w < 8; w++) s += ws[w];
        g_bsum[blockIdx.x] = s;
    }
}
__global__ void k_scan2() {
    int tid = threadIdx.x;
    int lane = tid & 31, wid = tid >> 5;
    int v = (tid < NB_SCAN) ? g_bsum[tid] : 0;
    int x = v;
#pragma unroll
    for (int o = 1; o < 32; o <<= 1) {
        int t = __shfl_up_sync(0xffffffff, x, o);
        if (lane >= o) x += t;
    }
    __shared__ int ws[8];
    if (lane == 31) ws[wid] = x;
    __syncthreads();
    if (wid == 0 && lane < 8) {
        int y = ws[lane];
#pragma unroll
        for (int o = 1; o < 8; o <<= 1) {
            int t = __shfl_up_sync(0xff, y, o);
            if (lane >= o) y += t;
        }
        ws[lane] = y;
    }
    __syncthreads();
    int prefix = wid ? ws[wid - 1] : 0;
    if (tid < NB_SCAN) g_boff[tid] = prefix + x - v;
}
__global__ void k_addback() {
    int tid = threadIdx.x;
    int i = blockIdx.x * 256 + tid;
    int v = (i < N_NODES) ? g_deg[i] : 0;
    int lane = tid & 31, wid = tid >> 5;
    int x = v;
#pragma unroll
    for (int o = 1; o < 32; o <<= 1) {
        int t = __shfl_up_sync(0xffffffff, x, o);
        if (lane >= o) x += t;
    }
    __shared__ int ws[8];
    if (lane == 31) ws[wid] = x;
    __syncthreads();
    if (wid == 0 && lane < 8) {
        int y = ws[lane];
#pragma unroll
        for (int o = 1; o < 8; o <<= 1) {
            int t = __shfl_up_sync(0xff, y, o);
            if (lane >= o) y += t;
        }
        ws[lane] = y;
    }
    __syncthreads();
    int prefix = (wid ? ws[wid - 1] : 0) + g_boff[blockIdx.x];
    int excl = prefix + x - v;
    if (i < N_NODES) { g_off[i] = excl; g_cur[i] = excl; }
    if (i == 0) g_off[N_NODES] = ET;
}
__global__ void k_fill(const int* __restrict__ ei) {
    int i = blockIdx.x * blockDim.x + threadIdx.x;
    if (i >= ET) return;
    int src, dst;
    if (i < N_EDGES) { src = ei[i]; dst = ei[N_EDGES + i]; }
    else { src = dst = i - N_EDGES; }
    int pos = atomicAdd(&g_cur[dst], 1);
    g_srcl[pos] = src;
}

// ================= weight conversion =================
__global__ void k_cvt_w(const float* __restrict__ W) {
    int i = blockIdx.x * blockDim.x + threadIdx.x;
    if (i >= N_NODES * H3 / 4) return;
    float4 v = ((const float4*)W)[i];
    __nv_bfloat162 lo = __floats2bfloat162_rn(v.x, v.y);
    __nv_bfloat162 hi = __floats2bfloat162_rn(v.z, v.w);
    ((__nv_bfloat162*)g_w16)[i * 2] = lo;
    ((__nv_bfloat162*)g_w16)[i * 2 + 1] = hi;
}

// ================= cp.async helpers =================
__device__ __forceinline__ void cp_async16(uint32_t saddr, const void* gptr, int srcBytes) {
    asm volatile("cp.async.cg.shared.global [%0], [%1], 16, %2;\n"
                 :: "r"(saddr), "l"(gptr), "r"(srcBytes));
}
__device__ __forceinline__ void cp_commit() {
    asm volatile("cp.async.commit_group;\n");
}
template <int NW>
__device__ __forceinline__ void cp_wait() {
    asm volatile("cp.async.wait_group %0;\n" :: "n"(NW));
}

// ================= mma wrappers =================
__device__ __forceinline__ void mma_tf32(float c[4], uint32_t a0, uint32_t a1,
                                         uint32_t a2, uint32_t a3,
                                         uint32_t b0, uint32_t b1) {
    asm volatile(
        "mma.sync.aligned.m16n8k8.row.col.f32.tf32.tf32.f32 "
        "{%0,%1,%2,%3}, {%4,%5,%6,%7}, {%8,%9}, {%0,%1,%2,%3};"
        : "+f"(c[0]), "+f"(c[1]), "+f"(c[2]), "+f"(c[3])
        : "r"(a0), "r"(a1), "r"(a2), "r"(a3), "r"(b0), "r"(b1));
}
__device__ __forceinline__ void mma_bf16(float c[4], uint32_t a0, uint32_t a1,
                                         uint32_t a2, uint32_t a3,
                                         uint32_t b0, uint32_t b1) {
    asm volatile(
        "mma.sync.aligned.m16n8k16.row.col.f32.bf16.bf16.f32 "
        "{%0,%1,%2,%3}, {%4,%5,%6,%7}, {%8,%9}, {%0,%1,%2,%3};"
        : "+f"(c[0]), "+f"(c[1]), "+f"(c[2]), "+f"(c[3])
        : "r"(a0), "r"(a1), "r"(a2), "r"(a3), "r"(b0), "r"(b1));
}

// ================= bf16 lin2 GEMM (single pass, fused LSE partials) =======
#define BPAD 72
#define BSTAGE (128 * BPAD)
#define LIN2_SMEM_B (4 * BSTAGE * 2)
__global__ __launch_bounds__(256) void k_mma_lin2(
    const float* __restrict__ bias, float* __restrict__ out)
{
    extern __shared__ __nv_bfloat16 smem16[];
    const int K = H3, Nn = N_NODES;
    __nv_bfloat16* Abuf = smem16;
    __nv_bfloat16* Bbuf = smem16 + 2 * BSTAGE;

    int tid = threadIdx.x;
    int warp = tid >> 5, lane = tid & 31;
    int wm = (warp & 1) * 64;
    int wnw = warp >> 1;
    int wn = wnw * 32;
    int bm = blockIdx.y * 128;
    int bn = blockIdx.x * 128;

    float c[4][4][4];
#pragma unroll
    for (int mt = 0; mt < 4; mt++)
#pragma unroll
        for (int nt = 0; nt < 4; nt++)
#pragma unroll
            for (int r = 0; r < 4; r++) c[mt][nt][r] = 0.f;

    int gr = lane >> 2, gc = lane & 3;

    auto load_tile = [&](int it, int stage) {
        int k0 = it * 64;
        __nv_bfloat16* Ad = Abuf + stage * BSTAGE;
        __nv_bfloat16* Bd = Bbuf + stage * BSTAGE;
#pragma unroll
        for (int l = 0; l < 4; l++) {
            int linear = tid + l * 256;
            int row = linear >> 3;
            int kc = (linear & 7) * 8;
            uint32_t sa = (uint32_t)__cvta_generic_to_shared(Ad + row * BPAD + kc);
            cp_async16(sa, g_z16 + (size_t)(bm + row) * K + k0 + kc, 16);
            int grow = bn + row;
            int ok = (grow < Nn);
            uint32_t sb = (uint32_t)__cvta_generic_to_shared(Bd + row * BPAD + kc);
            cp_async16(sb, g_w16 + (size_t)(ok ? grow : 0) * K + k0 + kc, ok ? 16 : 0);
        }
        cp_commit();
    };

    const int NIT = K / 64;
    load_tile(0, 0);
    for (int it = 0; it < NIT; it++) {
        int cur = it & 1;
        if (it + 1 < NIT) { load_tile(it + 1, cur ^ 1); cp_wait<1>(); }
        else cp_wait<0>();
        __syncthreads();

        const __nv_bfloat16* Ac = Abuf + cur * BSTAGE;
        const __nv_bfloat16* Bc = Bbuf + cur * BSTAGE;
#pragma unroll
        for (int ks = 0; ks < 4; ks++) {
            int kb = ks * 16;
            uint32_t a[4][4];
#pragma unroll
            for (int mt = 0; mt < 4; mt++) {
                int mrow = wm + mt * 16 + gr;
                a[mt][0] = *(const uint32_t*)&Ac[mrow * BPAD + kb + gc * 2];
                a[mt][1] = *(const uint32_t*)&Ac[(mrow + 8) * BPAD + kb + gc * 2];
                a[mt][2] = *(const uint32_t*)&Ac[mrow * BPAD + kb + 8 + gc * 2];
                a[mt][3] = *(const uint32_t*)&Ac[(mrow + 8) * BPAD + kb + 8 + gc * 2];
            }
            uint32_t b[4][2];
#pragma unroll
            for (int nt = 0; nt < 4; nt++) {
                int ncol = wn + nt * 8 + gr;
                b[nt][0] = *(const uint32_t*)&Bc[ncol * BPAD + kb + gc * 2];
                b[nt][1] = *(const uint32_t*)&Bc[ncol * BPAD + kb + 8 + gc * 2];
            }
#pragma unroll
            for (int mt = 0; mt < 4; mt++)
#pragma unroll
                for (int nt = 0; nt < 4; nt++)
                    mma_bf16(c[mt][nt], a[mt][0], a[mt][1], a[mt][2], a[mt][3],
                             b[nt][0], b[nt][1]);
        }
        __syncthreads();
    }

    float* smf   = (float*)smem16;
    float* sm_pm  = smf;
    float* sm_max = smf + 512;
    float* sm_ps  = smf + 512 + 128;

    int crow = lane >> 2, ccol = (lane & 3) * 2;
    float bv[4][2];
    bool ok[4][2];
#pragma unroll
    for (int nt = 0; nt < 4; nt++)
#pragma unroll
        for (int j = 0; j < 2; j++) {
            int col = bn + wn + nt * 8 + ccol + j;
            ok[nt][j] = (col < Nn);
            bv[nt][j] = ok[nt][j] ? bias[col] : 0.f;
        }

#pragma unroll
    for (int mt = 0; mt < 4; mt++) {
#pragma unroll
        for (int h = 0; h < 2; h++) {
            int lrow = wm + mt * 16 + crow + h * 8;
            int row = bm + lrow;
            float vmax = NEG_INF;
#pragma unroll
            for (int nt = 0; nt < 4; nt++)
#pragma unroll
                for (int j = 0; j < 2; j++) {
                    if (ok[nt][j]) {
                        float v = c[mt][nt][h * 2 + j] + bv[nt][j];
                        out[(size_t)row * Nn + (bn + wn + nt * 8 + ccol + j)] = v;
                        vmax = fmaxf(vmax, v);
                    }
                }
            vmax = fmaxf(vmax, __shfl_xor_sync(0xffffffff, vmax, 1));
            vmax = fmaxf(vmax, __shfl_xor_sync(0xffffffff, vmax, 2));
            if ((lane & 3) == 0) sm_pm[lrow * 4 + wnw] = vmax;
        }
    }
    __syncthreads();
    if (tid < 128) {
        float m = fmaxf(fmaxf(sm_pm[tid * 4], sm_pm[tid * 4 + 1]),
                        fmaxf(sm_pm[tid * 4 + 2], sm_pm[tid * 4 + 3]));
        sm_max[tid] = m;
    }
    __syncthreads();
#pragma unroll
    for (int mt = 0; mt < 4; mt++) {
#pragma unroll
        for (int h = 0; h < 2; h++) {
            int lrow = wm + mt * 16 + crow + h * 8;
            float M = sm_max[lrow];
            float ls = 0.f;
#pragma unroll
            for (int nt = 0; nt < 4; nt++)
#pragma unroll
                for (int j = 0; j < 2; j++)
                    if (ok[nt][j])
                        ls += __expf(c[mt][nt][h * 2 + j] + bv[nt][j] - M);
            ls += __shfl_xor_sync(0xffffffff, ls, 1);
            ls += __shfl_xor_sync(0xffffffff, ls, 2);
            if ((lane & 3) == 0) sm_ps[lrow * 4 + wnw] = ls;
        }
    }
    __syncthreads();
    if (tid < 128) {
        float s = sm_ps[tid * 4] + sm_ps[tid * 4 + 1] +
                  sm_ps[tid * 4 + 2] + sm_ps[tid * 4 + 3];
        g_pmax[(size_t)(bm + tid) * NT_TILES + blockIdx.x] = sm_max[tid];
        g_psum[(size_t)(bm + tid) * NT_TILES + blockIdx.x] = s;
    }
}

// ================= tf32 feature GEMM, fused attn dots, bf16 h output ======
#define MMA_PAD 36
#define MMA_STAGE_F (128 * MMA_PAD)
#define FEAT_SMEM_B (4 * MMA_STAGE_F * 4)
__global__ __launch_bounds__(256) void k_mma_feat(
    const float* __restrict__ Aext, const float* __restrict__ W,
    const float* __restrict__ asrc, const float* __restrict__ adst, int asel)
{
    extern __shared__ float smemf[];
    const float* A = asel ? g_hn : Aext;
    const int M = N_NODES, K = D;
    float* Abuf = smemf;
    float* Bbuf = smemf + 2 * MMA_STAGE_F;

    int tid = threadIdx.x;
    int warp = tid >> 5, lane = tid & 31;
    int wm = (warp & 1) * 64;
    int wnw = warp >> 1;
    int wn = wnw * 32;
    int bm = blockIdx.y * 128;

    float c[4][4][4];
#pragma unroll
    for (int mt = 0; mt < 4; mt++)
#pragma unroll
        for (int nt = 0; nt < 4; nt++)
#pragma unroll
            for (int r = 0; r < 4; r++) c[mt][nt][r] = 0.f;

    int gr = lane >> 2, gc = lane & 3;

    auto load_tile = [&](int it, int stage) {
        int k0 = it * 32;
        float* Ad = Abuf + stage * MMA_STAGE_F;
        float* Bd = Bbuf + stage * MMA_STAGE_F;
#pragma unroll
        for (int l = 0; l < 4; l++) {
            int linear = tid + l * 256;
            int row = linear >> 3;
            int kc = (linear & 7) * 4;
            int ar = bm + row;
            int okA = (ar < M);
            uint32_t sa = (uint32_t)__cvta_generic_to_shared(Ad + row * MMA_PAD + kc);
            cp_async16(sa, A + (size_t)(okA ? ar : 0) * K + k0 + kc, okA ? 16 : 0);
            uint32_t sbb = (uint32_t)__cvta_generic_to_shared(Bd + row * MMA_PAD + kc);
            cp_async16(sbb, W + (size_t)row * K + k0 + kc, 16);
        }
        cp_commit();
    };

    const int NIT = K / 32;
    load_tile(0, 0);
    for (int it = 0; it < NIT; it++) {
        int cur = it & 1;
        if (it + 1 < NIT) { load_tile(it + 1, cur ^ 1); cp_wait<1>(); }
        else cp_wait<0>();
        __syncthreads();

        const float* Ac = Abuf + cur * MMA_STAGE_F;
        const float* Bc = Bbuf + cur * MMA_STAGE_F;
#pragma unroll
        for (int ks = 0; ks < 4; ks++) {
            int kb = ks * 8;
            uint32_t a[4][4];
#pragma unroll
            for (int mt = 0; mt < 4; mt++) {
                int mrow = wm + mt * 16 + gr;
                a[mt][0] = __float_as_uint(Ac[mrow * MMA_PAD + kb + gc]);
                a[mt][1] = __float_as_uint(Ac[(mrow + 8) * MMA_PAD + kb + gc]);
                a[mt][2] = __float_as_uint(Ac[mrow * MMA_PAD + kb + gc + 4]);
                a[mt][3] = __float_as_uint(Ac[(mrow + 8) * MMA_PAD + kb + gc + 4]);
            }
            uint32_t b[4][2];
#pragma unroll
            for (int nt = 0; nt < 4; nt++) {
                int ncol = wn + nt * 8 + gr;
                b[nt][0] = __float_as_uint(Bc[ncol * MMA_PAD + kb + gc]);
                b[nt][1] = __float_as_uint(Bc[ncol * MMA_PAD + kb + gc + 4]);
            }
#pragma unroll
            for (int mt = 0; mt < 4; mt++)
#pragma unroll
                for (int nt = 0; nt < 4; nt++)
                    mma_tf32(c[mt][nt], a[mt][0], a[mt][1], a[mt][2], a[mt][3],
                             b[nt][0], b[nt][1]);
        }
        __syncthreads();
    }

    float* sm_as = smemf;
    float* sm_ad = smemf + 512;

    int crow = lane >> 2, ccol = (lane & 3) * 2;
    float av[4][2], dv[4][2];
#pragma unroll
    for (int nt = 0; nt < 4; nt++)
#pragma unroll
        for (int j = 0; j < 2; j++) {
            int col = wn + nt * 8 + ccol + j;
            av[nt][j] = asrc[col];
            dv[nt][j] = adst[col];
        }

#pragma unroll
    for (int mt = 0; mt < 4; mt++) {
#pragma unroll
        for (int h = 0; h < 2; h++) {
            int lrow = wm + mt * 16 + crow + h * 8;
            int row = bm + lrow;
            float pas = 0.f, pad = 0.f;
            if (row < M) {
#pragma unroll
                for (int nt = 0; nt < 4; nt++) {
                    float v0 = c[mt][nt][h * 2];
                    float v1 = c[mt][nt][h * 2 + 1];
                    int col = wn + nt * 8 + ccol;
                    *(__nv_bfloat162*)(g_h16 + (size_t)row * D + col) =
                        __floats2bfloat162_rn(v0, v1);
                    pas += v0 * av[nt][0] + v1 * av[nt][1];
                    pad += v0 * dv[nt][0] + v1 * dv[nt][1];
                }
            }
            pas += __shfl_xor_sync(0xffffffff, pas, 1);
            pas += __shfl_xor_sync(0xffffffff, pas, 2);
            pad += __shfl_xor_sync(0xffffffff, pad, 1);
            pad += __shfl_xor_sync(0xffffffff, pad, 2);
            if ((lane & 3) == 0) {
                sm_as[lrow * 4 + wnw] = pas;
                sm_ad[lrow * 4 + wnw] = pad;
            }
        }
    }
    __syncthreads();
    if (tid < 128) {
        int row = bm + tid;
        if (row < M) {
            g_as[row] = sm_as[tid * 4] + sm_as[tid * 4 + 1] +
                        sm_as[tid * 4 + 2] + sm_as[tid * 4 + 3];
            g_ad[row] = sm_ad[tid * 4] + sm_ad[tid * 4 + 1] +
                        sm_ad[tid * 4 + 2] + sm_ad[tid * 4 + 3];
        }
    }
}

// ================= fp32 SGEMM lin1 with fused gather =================
__global__ __launch_bounds__(256) void k_sgemm_lin1(
    const int* __restrict__ x, const float* __restrict__ Bm,
    const float* __restrict__ bias)
{
    const int Nn = H3, K = H3;
    float* C = g_z1;

    __shared__ float As[8][128];
    __shared__ float Bs[8][128];

    int tid = threadIdx.x;
    int tx = tid & 15, ty = tid >> 4;
    int bm = blockIdx.y * 128, bn = blockIdx.x * 128;

    float acc[8][8];
#pragma unroll
    for (int i = 0; i < 8; i++)
#pragma unroll
        for (int j = 0; j < 8; j++) acc[i][j] = 0.f;

    int lr = tid >> 1;
    int lk = (tid & 1) * 4;

    for (int k0 = 0; k0 < K; k0 += 8) {
        int ar = bm + lr;
        int kidx = k0 + lk;
        int node = x[ar * 3 + (kidx >> 7)];
        float4 a4 = *(const float4*)(g_hn + (size_t)node * D + (kidx & 127));
        As[lk + 0][lr] = a4.x; As[lk + 1][lr] = a4.y;
        As[lk + 2][lr] = a4.z; As[lk + 3][lr] = a4.w;

        float4 b4 = make_float4(0.f, 0.f, 0.f, 0.f);
        int br = bn + lr;
        if (br < Nn) b4 = *(const float4*)(Bm + (size_t)br * K + kidx);
        Bs[lk + 0][lr] = b4.x; Bs[lk + 1][lr] = b4.y;
        Bs[lk + 2][lr] = b4.z; Bs[lk + 3][lr] = b4.w;
        __syncthreads();

#pragma unroll
        for (int k = 0; k < 8; k++) {
            float4 a0 = *(const float4*)&As[k][ty * 8];
            float4 a1 = *(const float4*)&As[k][ty * 8 + 4];
            float4 b0 = *(const float4*)&Bs[k][tx * 8];
            float4 b1 = *(const float4*)&Bs[k][tx * 8 + 4];
            float a[8] = {a0.x, a0.y, a0.z, a0.w, a1.x, a1.y, a1.z, a1.w};
            float b[8] = {b0.x, b0.y, b0.z, b0.w, b1.x, b1.y, b1.z, b1.w};
#pragma unroll
            for (int i = 0; i < 8; i++)
#pragma unroll
                for (int j = 0; j < 8; j++) acc[i][j] += a[i] * b[j];
        }
        __syncthreads();
    }

#pragma unroll
    for (int i = 0; i < 8; i++) {
        int row = bm + ty * 8 + i;
#pragma unroll
        for (int j = 0; j < 8; j++) {
            int col = bn + tx * 8 + j;
            if (col < Nn) C[(size_t)row * Nn + col] = acc[i][j] + bias[col];
        }
    }
}

// ================= LSE merge + subtract =================
__global__ void k_reduce_lse() {
    int row = blockIdx.x * 8 + (threadIdx.x >> 5);
    int lane = threadIdx.x & 31;
    const float* pm = g_pmax + (size_t)row * NT_TILES;
    const float* ps = g_psum + (size_t)row * NT_TILES;
    float M = NEG_INF;
    for (int i = lane; i < NT_TILES; i += 32) M = fmaxf(M, pm[i]);
#pragma unroll
    for (int o = 16; o; o >>= 1) M = fmaxf(M, __shfl_xor_sync(0xffffffff, M, o));
    float S = 0.f;
    for (int i = lane; i < NT_TILES; i += 32) S += ps[i] * __expf(pm[i] - M);
#pragma unroll
    for (int o = 16; o; o >>= 1) S += __shfl_xor_sync(0xffffffff, S, o);
    if (lane == 0) g_lse[row] = M + logf(S);
}

__global__ void k_sub_lse(float* __restrict__ out) {
    int idx = blockIdx.x * blockDim.x + threadIdx.x;
    if (idx >= BQ * 12500) return;
    int row = idx / 12500;
    float l = g_lse[row];
    float4* p = (float4*)out + idx;
    float4 v = *p;
    v.x -= l; v.y -= l; v.z -= l; v.w -= l;
    *p = v;
}

// ================= per-node attention aggregate (fused colstats) ==========
// grid = 6250 blocks x 256 threads = exactly 50000 warps/nodes, no remainder
__global__ void k_node_attagg(int layer) {
    int gt = blockIdx.x * blockDim.x + threadIdx.x;
    int node = gt >> 5, lane = gt & 31;
    int tid = threadIdx.x;
    int beg = g_off[node], end = g_off[node + 1];
    float ad = g_ad[node];

    float m = NEG_INF;
    for (int i = beg + lane; i < end; i += 32) {
        float s = g_as[g_srcl[i]] + ad;
        float e = (s > 0.f) ? s : 0.2f * s;
        g_e[i] = e;
        m = fmaxf(m, e);
    }
#pragma unroll
    for (int o = 16; o; o >>= 1) m = fmaxf(m, __shfl_xor_sync(0xffffffff, m, o));
    __syncwarp();

    // fused exp + den + weighted gather; dual accumulators for ILP
    float4 acc_a = make_float4(0.f, 0.f, 0.f, 0.f);
    float4 acc_b = make_float4(0.f, 0.f, 0.f, 0.f);
    float den = 0.f;
    int coff = lane * 4;
    int i = beg;
    for (; i + 3 < end; i += 4) {
        float w0 = __expf(g_e[i] - m),     w1 = __expf(g_e[i + 1] - m);
        float w2 = __expf(g_e[i + 2] - m), w3 = __expf(g_e[i + 3] - m);
        den += (w0 + w1) + (w2 + w3);
        int s0 = g_srcl[i],     s1 = g_srcl[i + 1];
        int s2 = g_srcl[i + 2], s3 = g_srcl[i + 3];
        uint2 p0 = *(const uint2*)(g_h16 + (size_t)s0 * D + coff);
        uint2 p1 = *(const uint2*)(g_h16 + (size_t)s1 * D + coff);
        uint2 p2 = *(const uint2*)(g_h16 + (size_t)s2 * D + coff);
        uint2 p3 = *(const uint2*)(g_h16 + (size_t)s3 * D + coff);
        float2 a0 = __bfloat1622float2(*(__nv_bfloat162*)&p0.x);
        float2 b0 = __bfloat1622float2(*(__nv_bfloat162*)&p0.y);
        float2 a1 = __bfloat1622float2(*(__nv_bfloat162*)&p1.x);
        float2 b1 = __bfloat1622float2(*(__nv_bfloat162*)&p1.y);
        float2 a2 = __bfloat1622float2(*(__nv_bfloat162*)&p2.x);
        float2 b2 = __bfloat1622float2(*(__nv_bfloat162*)&p2.y);
        float2 a3 = __bfloat1622float2(*(__nv_bfloat162*)&p3.x);
        float2 b3 = __bfloat1622float2(*(__nv_bfloat162*)&p3.y);
        acc_a.x += w0 * a0.x + w1 * a1.x;
        acc_a.y += w0 * a0.y + w1 * a1.y;
        acc_a.z += w0 * b0.x + w1 * b1.x;
        acc_a.w += w0 * b0.y + w1 * b1.y;
        acc_b.x += w2 * a2.x + w3 * a3.x;
        acc_b.y += w2 * a2.y + w3 * a3.y;
        acc_b.z += w2 * b2.x + w3 * b3.x;
        acc_b.w += w2 * b2.y + w3 * b3.y;
    }
    for (; i < end; i++) {
        float w = __expf(g_e[i] - m);
        den += w;
        int s = g_srcl[i];
        uint2 p = *(const uint2*)(g_h16 + (size_t)s * D + coff);
        float2 a = __bfloat1622float2(*(__nv_bfloat162*)&p.x);
        float2 b = __bfloat1622float2(*(__nv_bfloat162*)&p.y);
        acc_a.x += w * a.x; acc_a.y += w * a.y;
        acc_a.z += w * b.x; acc_a.w += w * b.y;
    }
    float inv = 1.f / den;
    float4 acc;
    acc.x = (acc_a.x + acc_b.x) * inv;
    acc.y = (acc_a.y + acc_b.y) * inv;
    acc.z = (acc_a.z + acc_b.z) * inv;
    acc.w = (acc_a.w + acc_b.w) * inv;
    *(float4*)(g_agg + (size_t)node * D + coff) = acc;

    // ---- fused GraphNorm column stats (block = 8 nodes) ----
    __shared__ float ssum[128], ssum2[128];
    if (tid < 128) { ssum[tid] = 0.f; ssum2[tid] = 0.f; }
    __syncthreads();
    atomicAdd(&ssum[coff + 0], acc.x);
    atomicAdd(&ssum[coff + 1], acc.y);
    atomicAdd(&ssum[coff + 2], acc.z);
    atomicAdd(&ssum[coff + 3], acc.w);
    atomicAdd(&ssum2[coff + 0], acc.x * acc.x);
    atomicAdd(&ssum2[coff + 1], acc.y * acc.y);
    atomicAdd(&ssum2[coff + 2], acc.z * acc.z);
    atomicAdd(&ssum2[coff + 3], acc.w * acc.w);
    __syncthreads();
    if (tid < 128) {
        atomicAdd(&g_musum2[layer * D + tid], ssum[tid]);
        atomicAdd(&g_varsum2[layer * D + tid], ssum2[tid]);
    }
}

// ================= GraphNorm normalize =================
__global__ void k_normalize(const float* __restrict__ bb, const float* __restrict__ gw,
                            const float* __restrict__ gb, const float* __restrict__ ms,
                            int layer) {
    int idx = blockIdx.x * blockDim.x + threadIdx.x;
    if (idx >= N_NODES * D) return;
    int d = idx & (D - 1);
    float S1 = g_musum2[layer * D + d] * (1.f / N_NODES);
    float S2 = g_varsum2[layer * D + d] * (1.f / N_NODES);
    float bv = bb[d];
    float mu = S1 + bv;
    float cc = bv - mu * ms[d];
    float var = S2 + 2.f * cc * S1 + cc * cc;
    float istd = rsqrtf(var + EPSV);
    float t = g_agg[idx] + cc;
    float v = t * istd * gw[d] + gb[d];
    g_hn[idx] = v > 0.f ? v : 0.f;
}

// ================= head BN =================
__global__ void k_bn_relu(const float* __restrict__ bw, const float* __restrict__ bb) {
    int c = blockIdx.x;
    int t = threadIdx.x;
    __shared__ float sm[256], ss[256];
    float s = 0.f, s2 = 0.f;
    for (int r = t; r < BQ; r += 256) {
        float v = g_z1[r * H3 + c];
        s += v; s2 += v * v;
    }
    sm[t] = s; ss[t] = s2;
    __syncthreads();
    for (int o = 128; o; o >>= 1) {
        if (t < o) { sm[t] += sm[t + o]; ss[t] += ss[t + o]; }
        __syncthreads();
    }
    float mu = sm[0] * (1.f / BQ);
    float var = ss[0] * (1.f / BQ) - mu * mu;
    float istd = rsqrtf(var + EPSV);
    float w = bw[c], bias = bb[c];
    for (int r = t; r < BQ; r += 256) {
        float v = (g_z1[r * H3 + c] - mu) * istd * w + bias;
        g_z16[r * H3 + c] = __float2bfloat16(v > 0.f ? v : 0.f);
    }
}

// ================= host driver =================
extern "C" void kernel_launch(void* const* d_in, const int* in_sizes, int n_in,
                              void* d_out, int out_size)
{
    const int*   x       = (const int*)  d_in[0];
    const int*   ei      = (const int*)  d_in[1];
    const float* emb     = (const float*)d_in[2];
    const float* W1      = (const float*)d_in[3];
    const float* asrc1   = (const float*)d_in[4];
    const float* adst1   = (const float*)d_in[5];
    const float* b1      = (const float*)d_in[6];
    const float* gn1w    = (const float*)d_in[7];
    const float* gn1b    = (const float*)d_in[8];
    const float* gn1ms   = (const float*)d_in[9];
    const float* W2      = (const float*)d_in[10];
    const float* asrc2   = (const float*)d_in[11];
    const float* adst2   = (const float*)d_in[12];
    const float* b2      = (const float*)d_in[13];
    const float* gn2w    = (const float*)d_in[14];
    const float* gn2b    = (const float*)d_in[15];
    const float* gn2ms   = (const float*)d_in[16];
    const float* lin1W   = (const float*)d_in[17];
    const float* lin1b   = (const float*)d_in[18];
    const float* bnw     = (const float*)d_in[19];
    const float* bnb     = (const float*)d_in[20];
    const float* lin2W   = (const float*)d_in[21];
    const float* lin2b   = (const float*)d_in[22];
    float* out = (float*)d_out;

    cudaFuncSetAttribute(k_mma_lin2, cudaFuncAttributeMaxDynamicSharedMemorySize, LIN2_SMEM_B);
    cudaFuncSetAttribute(k_mma_feat, cudaFuncAttributeMaxDynamicSharedMemorySize, FEAT_SMEM_B);

    dim3 gf(1, NT_TILES);

    k_cvt_w<<<(N_NODES * H3 / 4 + 255) / 256, 256>>>(lin2W);
    k_zero_deg<<<(N_NODES + 255) / 256, 256>>>();
    k_count<<<(ET + 255) / 256, 256>>>(ei);
    k_bsums<<<NB_SCAN, 256>>>();
    k_scan2<<<1, 256>>>();
    k_mma_feat<<<gf, 256, FEAT_SMEM_B>>>(emb, W1, asrc1, adst1, 0);
    k_addback<<<NB_SCAN, 256>>>();
    k_fill<<<(ET + 255) / 256, 256>>>(ei);

    // --- layer 1 rest ---
    k_node_attagg<<<N_NODES / 8, 256>>>(0);
    k_normalize<<<(N_NODES * D + 255) / 256, 256>>>(b1, gn1w, gn1b, gn1ms, 0);

    // --- layer 2 ---
    k_mma_feat<<<gf, 256, FEAT_SMEM_B>>>(nullptr, W2, asrc2, adst2, 1);
    k_node_attagg<<<N_NODES / 8, 256>>>(1);
    k_normalize<<<(N_NODES * D + 255) / 256, 256>>>(b2, gn2w, gn2b, gn2ms, 1);

    // --- head ---
    dim3 gz1((H3 + 127) / 128, BQ / 128);
    k_sgemm_lin1<<<gz1, 256>>>(x, lin1W, lin1b);
    k_bn_relu<<<H3, 256>>>(bnw, bnb);
    dim3 gz2(NT_TILES, BQ / 128);
    k_mma_lin2<<<gz2, 256, LIN2_SMEM_B>>>(lin2b, out);
    k_reduce_lse<<<BQ / 8, 256>>>();
    k_sub_lse<<<(BQ * 12500 + 255) / 256, 256>>>(out);
}

// round 14
// speedup vs baseline: 1.0509x; 1.0509x over previous
#include <cuda_runtime.h>
#include <cuda_bf16.h>
#include <math.h>
#include <stdint.h>

#define N_NODES 50000
#define N_EDGES 800000
#define ET (N_EDGES + N_NODES)
#define D 128
#define BQ 1024
#define H3 384
#define EPSV 1e-5f
#define NT_TILES 391             // ceil(50000/128)
#define NB_SCAN 196              // ceil(50000/256)

#define NEG_INF (__int_as_float(0xff800000))

// ---------------- scratch (device globals; no allocation) ----------------
__device__ __nv_bfloat16 g_h16[(size_t)N_NODES * D];
__device__ float g_agg[N_NODES * D];
__device__ float g_hn[N_NODES * D];
__device__ float g_as[N_NODES];
__device__ float g_ad[N_NODES];
__device__ float g_e[ET];
__device__ float g_musum2[2 * D];
__device__ float g_varsum2[2 * D];
__device__ float g_z1[BQ * H3];
__device__ float g_lse[BQ];
__device__ float g_pmax[(size_t)BQ * NT_TILES];
__device__ float g_psum[(size_t)BQ * NT_TILES];
__device__ __nv_bfloat16 g_w16[(size_t)N_NODES * H3];
__device__ __nv_bfloat16 g_z16[BQ * H3];
// CSR
__device__ int g_deg[N_NODES];
__device__ int g_off[N_NODES + 1];
__device__ int g_cur[N_NODES];
__device__ int g_srcl[ET];
__device__ int g_bsum[NB_SCAN];
__device__ int g_boff[NB_SCAN];

// ================= CSR build =================
__global__ void k_zero_deg() {
    int i = blockIdx.x * blockDim.x + threadIdx.x;
    if (i < N_NODES) g_deg[i] = 0;
    if (i < 2 * D) { g_musum2[i] = 0.f; g_varsum2[i] = 0.f; }
}
__global__ void k_count(const int* __restrict__ ei) {
    int i = blockIdx.x * blockDim.x + threadIdx.x;
    if (i >= ET) return;
    int dst = (i < N_EDGES) ? ei[N_EDGES + i] : (i - N_EDGES);
    atomicAdd(&g_deg[dst], 1);
}
__global__ void k_bsums() {
    int tid = threadIdx.x;
    int i = blockIdx.x * 256 + tid;
    int v = (i < N_NODES) ? g_deg[i] : 0;
    int lane = tid & 31, wid = tid >> 5;
#pragma unroll
    for (int o = 16; o; o >>= 1) v += __shfl_down_sync(0xffffffff, v, o);
    __shared__ int ws[8];
    if (lane == 0) ws[wid] = v;
    __syncthreads();
    if (tid == 0) {
        int s = 0;
#pragma unroll
        for (int w = 0; w < 8; w++) s += ws[w];
        g_bsum[blockIdx.x] = s;
    }
}
__global__ void k_scan2() {
    int tid = threadIdx.x;
    int lane = tid & 31, wid = tid >> 5;
    int v = (tid < NB_SCAN) ? g_bsum[tid] : 0;
    int x = v;
#pragma unroll
    for (int o = 1; o < 32; o <<= 1) {
        int t = __shfl_up_sync(0xffffffff, x, o);
        if (lane >= o) x += t;
    }
    __shared__ int ws[8];
    if (lane == 31) ws[wid] = x;
    __syncthreads();
    if (wid == 0 && lane < 8) {
        int y = ws[lane];
#pragma unroll
        for (int o = 1; o < 8; o <<= 1) {
            int t = __shfl_up_sync(0xff, y, o);
            if (lane >= o) y += t;
        }
        ws[lane] = y;
    }
    __syncthreads();
    int prefix = wid ? ws[wid - 1] : 0;
    if (tid < NB_SCAN) g_boff[tid] = prefix + x - v;
}
__global__ void k_addback() {
    int tid = threadIdx.x;
    int i = blockIdx.x * 256 + tid;
    int v = (i < N_NODES) ? g_deg[i] : 0;
    int lane = tid & 31, wid = tid >> 5;
    int x = v;
#pragma unroll
    for (int o = 1; o < 32; o <<= 1) {
        int t = __shfl_up_sync(0xffffffff, x, o);
        if (lane >= o) x += t;
    }
    __shared__ int ws[8];
    if (lane == 31) ws[wid] = x;
    __syncthreads();
    if (wid == 0 && lane < 8) {
        int y = ws[lane];
#pragma unroll
        for (int o = 1; o < 8; o <<= 1) {
            int t = __shfl_up_sync(0xff, y, o);
            if (lane >= o) y += t;
        }
        ws[lane] = y;
    }
    __syncthreads();
    int prefix = (wid ? ws[wid - 1] : 0) + g_boff[blockIdx.x];
    int excl = prefix + x - v;
    if (i < N_NODES) { g_off[i] = excl; g_cur[i] = excl; }
    if (i == 0) g_off[N_NODES] = ET;
}
__global__ void k_fill(const int* __restrict__ ei) {
    int i = blockIdx.x * blockDim.x + threadIdx.x;
    if (i >= ET) return;
    int src, dst;
    if (i < N_EDGES) { src = ei[i]; dst = ei[N_EDGES + i]; }
    else { src = dst = i - N_EDGES; }
    int pos = atomicAdd(&g_cur[dst], 1);
    g_srcl[pos] = src;
}

// ================= weight conversion =================
__global__ void k_cvt_w(const float* __restrict__ W) {
    int i = blockIdx.x * blockDim.x + threadIdx.x;
    if (i >= N_NODES * H3 / 4) return;
    float4 v = ((const float4*)W)[i];
    __nv_bfloat162 lo = __floats2bfloat162_rn(v.x, v.y);
    __nv_bfloat162 hi = __floats2bfloat162_rn(v.z, v.w);
    ((__nv_bfloat162*)g_w16)[i * 2] = lo;
    ((__nv_bfloat162*)g_w16)[i * 2 + 1] = hi;
}

// ================= cp.async helpers =================
__device__ __forceinline__ void cp_async16(uint32_t saddr, const void* gptr, int srcBytes) {
    asm volatile("cp.async.cg.shared.global [%0], [%1], 16, %2;\n"
                 :: "r"(saddr), "l"(gptr), "r"(srcBytes));
}
__device__ __forceinline__ void cp_commit() {
    asm volatile("cp.async.commit_group;\n");
}
template <int NW>
__device__ __forceinline__ void cp_wait() {
    asm volatile("cp.async.wait_group %0;\n" :: "n"(NW));
}

// ================= mma wrappers =================
__device__ __forceinline__ void mma_tf32(float c[4], uint32_t a0, uint32_t a1,
                                         uint32_t a2, uint32_t a3,
                                         uint32_t b0, uint32_t b1) {
    asm volatile(
        "mma.sync.aligned.m16n8k8.row.col.f32.tf32.tf32.f32 "
        "{%0,%1,%2,%3}, {%4,%5,%6,%7}, {%8,%9}, {%0,%1,%2,%3};"
        : "+f"(c[0]), "+f"(c[1]), "+f"(c[2]), "+f"(c[3])
        : "r"(a0), "r"(a1), "r"(a2), "r"(a3), "r"(b0), "r"(b1));
}
__device__ __forceinline__ void mma_bf16(float c[4], uint32_t a0, uint32_t a1,
                                         uint32_t a2, uint32_t a3,
                                         uint32_t b0, uint32_t b1) {
    asm volatile(
        "mma.sync.aligned.m16n8k16.row.col.f32.bf16.bf16.f32 "
        "{%0,%1,%2,%3}, {%4,%5,%6,%7}, {%8,%9}, {%0,%1,%2,%3};"
        : "+f"(c[0]), "+f"(c[1]), "+f"(c[2]), "+f"(c[3])
        : "r"(a0), "r"(a1), "r"(a2), "r"(a3), "r"(b0), "r"(b1));
}

// ================= bf16 lin2 GEMM (single pass, fused LSE partials) =======
#define BPAD 72
#define BSTAGE (128 * BPAD)
#define LIN2_SMEM_B (4 * BSTAGE * 2)
__global__ void __launch_bounds__(256, 2) k_mma_lin2(
    const float* __restrict__ bias, float* __restrict__ out)
{
    extern __shared__ __nv_bfloat16 smem16[];
    const int K = H3, Nn = N_NODES;
    __nv_bfloat16* Abuf = smem16;
    __nv_bfloat16* Bbuf = smem16 + 2 * BSTAGE;

    int tid = threadIdx.x;
    int warp = tid >> 5, lane = tid & 31;
    int wm = (warp & 1) * 64;
    int wnw = warp >> 1;
    int wn = wnw * 32;
    int bm = blockIdx.y * 128;
    int bn = blockIdx.x * 128;

    float c[4][4][4];
#pragma unroll
    for (int mt = 0; mt < 4; mt++)
#pragma unroll
        for (int nt = 0; nt < 4; nt++)
#pragma unroll
            for (int r = 0; r < 4; r++) c[mt][nt][r] = 0.f;

    int gr = lane >> 2, gc = lane & 3;

    auto load_tile = [&](int it, int stage) {
        int k0 = it * 64;
        __nv_bfloat16* Ad = Abuf + stage * BSTAGE;
        __nv_bfloat16* Bd = Bbuf + stage * BSTAGE;
#pragma unroll
        for (int l = 0; l < 4; l++) {
            int linear = tid + l * 256;
            int row = linear >> 3;
            int kc = (linear & 7) * 8;
            uint32_t sa = (uint32_t)__cvta_generic_to_shared(Ad + row * BPAD + kc);
            cp_async16(sa, g_z16 + (size_t)(bm + row) * K + k0 + kc, 16);
            int grow = bn + row;
            int ok = (grow < Nn);
            uint32_t sb = (uint32_t)__cvta_generic_to_shared(Bd + row * BPAD + kc);
            cp_async16(sb, g_w16 + (size_t)(ok ? grow : 0) * K + k0 + kc, ok ? 16 : 0);
        }
        cp_commit();
    };

    const int NIT = K / 64;
    load_tile(0, 0);
    for (int it = 0; it < NIT; it++) {
        int cur = it & 1;
        if (it + 1 < NIT) { load_tile(it + 1, cur ^ 1); cp_wait<1>(); }
        else cp_wait<0>();
        __syncthreads();

        const __nv_bfloat16* Ac = Abuf + cur * BSTAGE;
        const __nv_bfloat16* Bc = Bbuf + cur * BSTAGE;
#pragma unroll
        for (int ks = 0; ks < 4; ks++) {
            int kb = ks * 16;
            uint32_t a[4][4];
#pragma unroll
            for (int mt = 0; mt < 4; mt++) {
                int mrow = wm + mt * 16 + gr;
                a[mt][0] = *(const uint32_t*)&Ac[mrow * BPAD + kb + gc * 2];
                a[mt][1] = *(const uint32_t*)&Ac[(mrow + 8) * BPAD + kb + gc * 2];
                a[mt][2] = *(const uint32_t*)&Ac[mrow * BPAD + kb + 8 + gc * 2];
                a[mt][3] = *(const uint32_t*)&Ac[(mrow + 8) * BPAD + kb + 8 + gc * 2];
            }
            uint32_t b[4][2];
#pragma unroll
            for (int nt = 0; nt < 4; nt++) {
                int ncol = wn + nt * 8 + gr;
                b[nt][0] = *(const uint32_t*)&Bc[ncol * BPAD + kb + gc * 2];
                b[nt][1] = *(const uint32_t*)&Bc[ncol * BPAD + kb + 8 + gc * 2];
            }
#pragma unroll
            for (int mt = 0; mt < 4; mt++)
#pragma unroll
                for (int nt = 0; nt < 4; nt++)
                    mma_bf16(c[mt][nt], a[mt][0], a[mt][1], a[mt][2], a[mt][3],
                             b[nt][0], b[nt][1]);
        }
        __syncthreads();
    }

    float* smf   = (float*)smem16;
    float* sm_pm  = smf;
    float* sm_max = smf + 512;
    float* sm_ps  = smf + 512 + 128;

    int crow = lane >> 2, ccol = (lane & 3) * 2;
    float bv[4][2];
    bool ok[4][2];
#pragma unroll
    for (int nt = 0; nt < 4; nt++)
#pragma unroll
        for (int j = 0; j < 2; j++) {
            int col = bn + wn + nt * 8 + ccol + j;
            ok[nt][j] = (col < Nn);
            bv[nt][j] = ok[nt][j] ? bias[col] : 0.f;
        }

#pragma unroll
    for (int mt = 0; mt < 4; mt++) {
#pragma unroll
        for (int h = 0; h < 2; h++) {
            int lrow = wm + mt * 16 + crow + h * 8;
            int row = bm + lrow;
            float vmax = NEG_INF;
#pragma unroll
            for (int nt = 0; nt < 4; nt++)
#pragma unroll
                for (int j = 0; j < 2; j++) {
                    if (ok[nt][j]) {
                        float v = c[mt][nt][h * 2 + j] + bv[nt][j];
                        out[(size_t)row * Nn + (bn + wn + nt * 8 + ccol + j)] = v;
                        vmax = fmaxf(vmax, v);
                    }
                }
            vmax = fmaxf(vmax, __shfl_xor_sync(0xffffffff, vmax, 1));
            vmax = fmaxf(vmax, __shfl_xor_sync(0xffffffff, vmax, 2));
            if ((lane & 3) == 0) sm_pm[lrow * 4 + wnw] = vmax;
        }
    }
    __syncthreads();
    if (tid < 128) {
        float m = fmaxf(fmaxf(sm_pm[tid * 4], sm_pm[tid * 4 + 1]),
                        fmaxf(sm_pm[tid * 4 + 2], sm_pm[tid * 4 + 3]));
        sm_max[tid] = m;
    }
    __syncthreads();
#pragma unroll
    for (int mt = 0; mt < 4; mt++) {
#pragma unroll
        for (int h = 0; h < 2; h++) {
            int lrow = wm + mt * 16 + crow + h * 8;
            float M = sm_max[lrow];
            float ls = 0.f;
#pragma unroll
            for (int nt = 0; nt < 4; nt++)
#pragma unroll
                for (int j = 0; j < 2; j++)
                    if (ok[nt][j])
                        ls += __expf(c[mt][nt][h * 2 + j] + bv[nt][j] - M);
            ls += __shfl_xor_sync(0xffffffff, ls, 1);
            ls += __shfl_xor_sync(0xffffffff, ls, 2);
            if ((lane & 3) == 0) sm_ps[lrow * 4 + wnw] = ls;
        }
    }
    __syncthreads();
    if (tid < 128) {
        float s = sm_ps[tid * 4] + sm_ps[tid * 4 + 1] +
                  sm_ps[tid * 4 + 2] + sm_ps[tid * 4 + 3];
        g_pmax[(size_t)(bm + tid) * NT_TILES + blockIdx.x] = sm_max[tid];
        g_psum[(size_t)(bm + tid) * NT_TILES + blockIdx.x] = s;
    }
}

// ================= tf32 feature GEMM, fused attn dots, bf16 h output ======
#define MMA_PAD 36
#define MMA_STAGE_F (128 * MMA_PAD)
#define FEAT_SMEM_B (4 * MMA_STAGE_F * 4)
__global__ void __launch_bounds__(256, 2) k_mma_feat(
    const float* __restrict__ Aext, const float* __restrict__ W,
    const float* __restrict__ asrc, const float* __restrict__ adst, int asel)
{
    extern __shared__ float smemf[];
    const float* A = asel ? g_hn : Aext;
    const int M = N_NODES, K = D;
    float* Abuf = smemf;
    float* Bbuf = smemf + 2 * MMA_STAGE_F;

    int tid = threadIdx.x;
    int warp = tid >> 5, lane = tid & 31;
    int wm = (warp & 1) * 64;
    int wnw = warp >> 1;
    int wn = wnw * 32;
    int bm = blockIdx.y * 128;

    float c[4][4][4];
#pragma unroll
    for (int mt = 0; mt < 4; mt++)
#pragma unroll
        for (int nt = 0; nt < 4; nt++)
#pragma unroll
            for (int r = 0; r < 4; r++) c[mt][nt][r] = 0.f;

    int gr = lane >> 2, gc = lane & 3;

    auto load_tile = [&](int it, int stage) {
        int k0 = it * 32;
        float* Ad = Abuf + stage * MMA_STAGE_F;
        float* Bd = Bbuf + stage * MMA_STAGE_F;
#pragma unroll
        for (int l = 0; l < 4; l++) {
            int linear = tid + l * 256;
            int row = linear >> 3;
            int kc = (linear & 7) * 4;
            int ar = bm + row;
            int okA = (ar < M);
            uint32_t sa = (uint32_t)__cvta_generic_to_shared(Ad + row * MMA_PAD + kc);
            cp_async16(sa, A + (size_t)(okA ? ar : 0) * K + k0 + kc, okA ? 16 : 0);
            uint32_t sbb = (uint32_t)__cvta_generic_to_shared(Bd + row * MMA_PAD + kc);
            cp_async16(sbb, W + (size_t)row * K + k0 + kc, 16);
        }
        cp_commit();
    };

    const int NIT = K / 32;
    load_tile(0, 0);
    for (int it = 0; it < NIT; it++) {
        int cur = it & 1;
        if (it + 1 < NIT) { load_tile(it + 1, cur ^ 1); cp_wait<1>(); }
        else cp_wait<0>();
        __syncthreads();

        const float* Ac = Abuf + cur * MMA_STAGE_F;
        const float* Bc = Bbuf + cur * MMA_STAGE_F;
#pragma unroll
        for (int ks = 0; ks < 4; ks++) {
            int kb = ks * 8;
            uint32_t a[4][4];
#pragma unroll
            for (int mt = 0; mt < 4; mt++) {
                int mrow = wm + mt * 16 + gr;
                a[mt][0] = __float_as_uint(Ac[mrow * MMA_PAD + kb + gc]);
                a[mt][1] = __float_as_uint(Ac[(mrow + 8) * MMA_PAD + kb + gc]);
                a[mt][2] = __float_as_uint(Ac[mrow * MMA_PAD + kb + gc + 4]);
                a[mt][3] = __float_as_uint(Ac[(mrow + 8) * MMA_PAD + kb + gc + 4]);
            }
            uint32_t b[4][2];
#pragma unroll
            for (int nt = 0; nt < 4; nt++) {
                int ncol = wn + nt * 8 + gr;
                b[nt][0] = __float_as_uint(Bc[ncol * MMA_PAD + kb + gc]);
                b[nt][1] = __float_as_uint(Bc[ncol * MMA_PAD + kb + gc + 4]);
            }
#pragma unroll
            for (int mt = 0; mt < 4; mt++)
#pragma unroll
                for (int nt = 0; nt < 4; nt++)
                    mma_tf32(c[mt][nt], a[mt][0], a[mt][1], a[mt][2], a[mt][3],
                             b[nt][0], b[nt][1]);
        }
        __syncthreads();
    }

    float* sm_as = smemf;
    float* sm_ad = smemf + 512;

    int crow = lane >> 2, ccol = (lane & 3) * 2;
    float av[4][2], dv[4][2];
#pragma unroll
    for (int nt = 0; nt < 4; nt++)
#pragma unroll
        for (int j = 0; j < 2; j++) {
            int col = wn + nt * 8 + ccol + j;
            av[nt][j] = asrc[col];
            dv[nt][j] = adst[col];
        }

#pragma unroll
    for (int mt = 0; mt < 4; mt++) {
#pragma unroll
        for (int h = 0; h < 2; h++) {
            int lrow = wm + mt * 16 + crow + h * 8;
            int row = bm + lrow;
            float pas = 0.f, pad = 0.f;
            if (row < M) {
#pragma unroll
                for (int nt = 0; nt < 4; nt++) {
                    float v0 = c[mt][nt][h * 2];
                    float v1 = c[mt][nt][h * 2 + 1];
                    int col = wn + nt * 8 + ccol;
                    *(__nv_bfloat162*)(g_h16 + (size_t)row * D + col) =
                        __floats2bfloat162_rn(v0, v1);
                    pas += v0 * av[nt][0] + v1 * av[nt][1];
                    pad += v0 * dv[nt][0] + v1 * dv[nt][1];
                }
            }
            pas += __shfl_xor_sync(0xffffffff, pas, 1);
            pas += __shfl_xor_sync(0xffffffff, pas, 2);
            pad += __shfl_xor_sync(0xffffffff, pad, 1);
            pad += __shfl_xor_sync(0xffffffff, pad, 2);
            if ((lane & 3) == 0) {
                sm_as[lrow * 4 + wnw] = pas;
                sm_ad[lrow * 4 + wnw] = pad;
            }
        }
    }
    __syncthreads();
    if (tid < 128) {
        int row = bm + tid;
        if (row < M) {
            g_as[row] = sm_as[tid * 4] + sm_as[tid * 4 + 1] +
                        sm_as[tid * 4 + 2] + sm_as[tid * 4 + 3];
            g_ad[row] = sm_ad[tid * 4] + sm_ad[tid * 4 + 1] +
                        sm_ad[tid * 4 + 2] + sm_ad[tid * 4 + 3];
        }
    }
}

// ================= fp32 SGEMM lin1 with fused gather =================
__global__ __launch_bounds__(256) void k_sgemm_lin1(
    const int* __restrict__ x, const float* __restrict__ Bm,
    const float* __restrict__ bias)
{
    const int Nn = H3, K = H3;
    float* C = g_z1;

    __shared__ float As[8][128];
    __shared__ float Bs[8][128];

    int tid = threadIdx.x;
    int tx = tid & 15, ty = tid >> 4;
    int bm = blockIdx.y * 128, bn = blockIdx.x * 128;

    float acc[8][8];
#pragma unroll
    for (int i = 0; i < 8; i++)
#pragma unroll
        for (int j = 0; j < 8; j++) acc[i][j] = 0.f;

    int lr = tid >> 1;
    int lk = (tid & 1) * 4;

    for (int k0 = 0; k0 < K; k0 += 8) {
        int ar = bm + lr;
        int kidx = k0 + lk;
        int node = x[ar * 3 + (kidx >> 7)];
        float4 a4 = *(const float4*)(g_hn + (size_t)node * D + (kidx & 127));
        As[lk + 0][lr] = a4.x; As[lk + 1][lr] = a4.y;
        As[lk + 2][lr] = a4.z; As[lk + 3][lr] = a4.w;

        float4 b4 = make_float4(0.f, 0.f, 0.f, 0.f);
        int br = bn + lr;
        if (br < Nn) b4 = *(const float4*)(Bm + (size_t)br * K + kidx);
        Bs[lk + 0][lr] = b4.x; Bs[lk + 1][lr] = b4.y;
        Bs[lk + 2][lr] = b4.z; Bs[lk + 3][lr] = b4.w;
        __syncthreads();

#pragma unroll
        for (int k = 0; k < 8; k++) {
            float4 a0 = *(const float4*)&As[k][ty * 8];
            float4 a1 = *(const float4*)&As[k][ty * 8 + 4];
            float4 b0 = *(const float4*)&Bs[k][tx * 8];
            float4 b1 = *(const float4*)&Bs[k][tx * 8 + 4];
            float a[8] = {a0.x, a0.y, a0.z, a0.w, a1.x, a1.y, a1.z, a1.w};
            float b[8] = {b0.x, b0.y, b0.z, b0.w, b1.x, b1.y, b1.z, b1.w};
#pragma unroll
            for (int i = 0; i < 8; i++)
#pragma unroll
                for (int j = 0; j < 8; j++) acc[i][j] += a[i] * b[j];
        }
        __syncthreads();
    }

#pragma unroll
    for (int i = 0; i < 8; i++) {
        int row = bm + ty * 8 + i;
#pragma unroll
        for (int j = 0; j < 8; j++) {
            int col = bn + tx * 8 + j;
            if (col < Nn) C[(size_t)row * Nn + col] = acc[i][j] + bias[col];
        }
    }
}

// ================= LSE merge + subtract =================
__global__ void k_reduce_lse() {
    int row = blockIdx.x * 8 + (threadIdx.x >> 5);
    int lane = threadIdx.x & 31;
    const float* pm = g_pmax + (size_t)row * NT_TILES;
    const float* ps = g_psum + (size_t)row * NT_TILES;
    float M = NEG_INF;
    for (int i = lane; i < NT_TILES; i += 32) M = fmaxf(M, pm[i]);
#pragma unroll
    for (int o = 16; o; o >>= 1) M = fmaxf(M, __shfl_xor_sync(0xffffffff, M, o));
    float S = 0.f;
    for (int i = lane; i < NT_TILES; i += 32) S += ps[i] * __expf(pm[i] - M);
#pragma unroll
    for (int o = 16; o; o >>= 1) S += __shfl_xor_sync(0xffffffff, S, o);
    if (lane == 0) g_lse[row] = M + logf(S);
}

__global__ void k_sub_lse(float* __restrict__ out) {
    int idx = blockIdx.x * blockDim.x + threadIdx.x;
    if (idx >= BQ * 12500) return;
    int row = idx / 12500;
    float l = g_lse[row];
    float4* p = (float4*)out + idx;
    float4 v = *p;
    v.x -= l; v.y -= l; v.z -= l; v.w -= l;
    *p = v;
}

// ================= per-node attention aggregate (fused expsum) ============
__global__ void k_node_attagg() {
    int gt = blockIdx.x * blockDim.x + threadIdx.x;
    int node = gt >> 5, lane = gt & 31;
    if (node >= N_NODES) return;
    int beg = g_off[node], end = g_off[node + 1];
    float ad = g_ad[node];

    float m = NEG_INF;
    for (int i = beg + lane; i < end; i += 32) {
        float s = g_as[g_srcl[i]] + ad;
        float e = (s > 0.f) ? s : 0.2f * s;
        g_e[i] = e;
        m = fmaxf(m, e);
    }
#pragma unroll
    for (int o = 16; o; o >>= 1) m = fmaxf(m, __shfl_xor_sync(0xffffffff, m, o));
    __syncwarp();

    float4 acc = make_float4(0.f, 0.f, 0.f, 0.f);
    float den = 0.f;
    int coff = lane * 4;
    int i = beg;
    for (; i + 3 < end; i += 4) {
        float w0 = __expf(g_e[i] - m),     w1 = __expf(g_e[i + 1] - m);
        float w2 = __expf(g_e[i + 2] - m), w3 = __expf(g_e[i + 3] - m);
        den += (w0 + w1) + (w2 + w3);
        int s0 = g_srcl[i],     s1 = g_srcl[i + 1];
        int s2 = g_srcl[i + 2], s3 = g_srcl[i + 3];
        uint2 p0 = *(const uint2*)(g_h16 + (size_t)s0 * D + coff);
        uint2 p1 = *(const uint2*)(g_h16 + (size_t)s1 * D + coff);
        uint2 p2 = *(const uint2*)(g_h16 + (size_t)s2 * D + coff);
        uint2 p3 = *(const uint2*)(g_h16 + (size_t)s3 * D + coff);
        float2 a0 = __bfloat1622float2(*(__nv_bfloat162*)&p0.x);
        float2 b0 = __bfloat1622float2(*(__nv_bfloat162*)&p0.y);
        float2 a1 = __bfloat1622float2(*(__nv_bfloat162*)&p1.x);
        float2 b1 = __bfloat1622float2(*(__nv_bfloat162*)&p1.y);
        float2 a2 = __bfloat1622float2(*(__nv_bfloat162*)&p2.x);
        float2 b2 = __bfloat1622float2(*(__nv_bfloat162*)&p2.y);
        float2 a3 = __bfloat1622float2(*(__nv_bfloat162*)&p3.x);
        float2 b3 = __bfloat1622float2(*(__nv_bfloat162*)&p3.y);
        acc.x += w0 * a0.x + w1 * a1.x + w2 * a2.x + w3 * a3.x;
        acc.y += w0 * a0.y + w1 * a1.y + w2 * a2.y + w3 * a3.y;
        acc.z += w0 * b0.x + w1 * b1.x + w2 * b2.x + w3 * b3.x;
        acc.w += w0 * b0.y + w1 * b1.y + w2 * b2.y + w3 * b3.y;
    }
    for (; i < end; i++) {
        float w = __expf(g_e[i] - m);
        den += w;
        int s = g_srcl[i];
        uint2 p = *(const uint2*)(g_h16 + (size_t)s * D + coff);
        float2 a = __bfloat1622float2(*(__nv_bfloat162*)&p.x);
        float2 b = __bfloat1622float2(*(__nv_bfloat162*)&p.y);
        acc.x += w * a.x; acc.y += w * a.y;
        acc.z += w * b.x; acc.w += w * b.y;
    }
    float inv = 1.f / den;
    acc.x *= inv; acc.y *= inv; acc.z *= inv; acc.w *= inv;
    *(float4*)(g_agg + (size_t)node * D + coff) = acc;
}

// ================= GraphNorm =================
#define RPB 64
__global__ void k_colstats(int layer) {
    int col = threadIdx.x;
    int r0 = blockIdx.x * RPB;
    int r1 = min(r0 + RPB, N_NODES);
    float s = 0.f, s2 = 0.f;
    for (int r = r0; r < r1; r++) {
        float a = g_agg[(size_t)r * D + col];
        s += a; s2 += a * a;
    }
    atomicAdd(&g_musum2[layer * D + col], s);
    atomicAdd(&g_varsum2[layer * D + col], s2);
}
__global__ void k_normalize(const float* __restrict__ bb, const float* __restrict__ gw,
                            const float* __restrict__ gb, const float* __restrict__ ms,
                            int layer) {
    int idx = blockIdx.x * blockDim.x + threadIdx.x;
    if (idx >= N_NODES * D) return;
    int d = idx & (D - 1);
    float S1 = g_musum2[layer * D + d] * (1.f / N_NODES);
    float S2 = g_varsum2[layer * D + d] * (1.f / N_NODES);
    float bv = bb[d];
    float mu = S1 + bv;
    float cc = bv - mu * ms[d];
    float var = S2 + 2.f * cc * S1 + cc * cc;
    float istd = rsqrtf(var + EPSV);
    float t = g_agg[idx] + cc;
    float v = t * istd * gw[d] + gb[d];
    g_hn[idx] = v > 0.f ? v : 0.f;
}

// ================= head BN =================
__global__ void k_bn_relu(const float* __restrict__ bw, const float* __restrict__ bb) {
    int c = blockIdx.x;
    int t = threadIdx.x;
    __shared__ float sm[256], ss[256];
    float s = 0.f, s2 = 0.f;
    for (int r = t; r < BQ; r += 256) {
        float v = g_z1[r * H3 + c];
        s += v; s2 += v * v;
    }
    sm[t] = s; ss[t] = s2;
    __syncthreads();
    for (int o = 128; o; o >>= 1) {
        if (t < o) { sm[t] += sm[t + o]; ss[t] += ss[t + o]; }
        __syncthreads();
    }
    float mu = sm[0] * (1.f / BQ);
    float var = ss[0] * (1.f / BQ) - mu * mu;
    float istd = rsqrtf(var + EPSV);
    float w = bw[c], bias = bb[c];
    for (int r = t; r < BQ; r += 256) {
        float v = (g_z1[r * H3 + c] - mu) * istd * w + bias;
        g_z16[r * H3 + c] = __float2bfloat16(v > 0.f ? v : 0.f);
    }
}

// ================= host driver =================
extern "C" void kernel_launch(void* const* d_in, const int* in_sizes, int n_in,
                              void* d_out, int out_size)
{
    const int*   x       = (const int*)  d_in[0];
    const int*   ei      = (const int*)  d_in[1];
    const float* emb     = (const float*)d_in[2];
    const float* W1      = (const float*)d_in[3];
    const float* asrc1   = (const float*)d_in[4];
    const float* adst1   = (const float*)d_in[5];
    const float* b1      = (const float*)d_in[6];
    const float* gn1w    = (const float*)d_in[7];
    const float* gn1b    = (const float*)d_in[8];
    const float* gn1ms   = (const float*)d_in[9];
    const float* W2      = (const float*)d_in[10];
    const float* asrc2   = (const float*)d_in[11];
    const float* adst2   = (const float*)d_in[12];
    const float* b2      = (const float*)d_in[13];
    const float* gn2w    = (const float*)d_in[14];
    const float* gn2b    = (const float*)d_in[15];
    const float* gn2ms   = (const float*)d_in[16];
    const float* lin1W   = (const float*)d_in[17];
    const float* lin1b   = (const float*)d_in[18];
    const float* bnw     = (const float*)d_in[19];
    const float* bnb     = (const float*)d_in[20];
    const float* lin2W   = (const float*)d_in[21];
    const float* lin2b   = (const float*)d_in[22];
    float* out = (float*)d_out;

    cudaFuncSetAttribute(k_mma_lin2, cudaFuncAttributeMaxDynamicSharedMemorySize, LIN2_SMEM_B);
    cudaFuncSetAttribute(k_mma_feat, cudaFuncAttributeMaxDynamicSharedMemorySize, FEAT_SMEM_B);

    dim3 gf(1, NT_TILES);

    k_cvt_w<<<(N_NODES * H3 / 4 + 255) / 256, 256>>>(lin2W);
    k_zero_deg<<<(N_NODES + 255) / 256, 256>>>();
    k_count<<<(ET + 255) / 256, 256>>>(ei);
    k_bsums<<<NB_SCAN, 256>>>();
    k_scan2<<<1, 256>>>();
    k_mma_feat<<<gf, 256, FEAT_SMEM_B>>>(emb, W1, asrc1, adst1, 0);
    k_addback<<<NB_SCAN, 256>>>();
    k_fill<<<(ET + 255) / 256, 256>>>(ei);

    // --- layer 1 rest ---
    k_node_attagg<<<(N_NODES * 32 + 255) / 256, 256>>>();
    k_colstats<<<(N_NODES + RPB - 1) / RPB, D>>>(0);
    k_normalize<<<(N_NODES * D + 255) / 256, 256>>>(b1, gn1w, gn1b, gn1ms, 0);

    // --- layer 2 ---
    k_mma_feat<<<gf, 256, FEAT_SMEM_B>>>(nullptr, W2, asrc2, adst2, 1);
    k_node_attagg<<<(N_NODES * 32 + 255) / 256, 256>>>();
    k_colstats<<<(N_NODES + RPB - 1) / RPB, D>>>(1);
    k_normalize<<<(N_NODES * D + 255) / 256, 256>>>(b2, gn2w, gn2b, gn2ms, 1);

    // --- head ---
    dim3 gz1((H3 + 127) / 128, BQ / 128);
    k_sgemm_lin1<<<gz1, 256>>>(x, lin1W, lin1b);
    k_bn_relu<<<H3, 256>>>(bnw, bnb);
    dim3 gz2(NT_TILES, BQ / 128);
    k_mma_lin2<<<gz2, 256, LIN2_SMEM_B>>>(lin2b, out);
    k_reduce_lse<<<BQ / 8, 256>>>();
    k_sub_lse<<<(BQ * 12500 + 255) / 256, 256>>>(out);
}

// round 15
// speedup vs baseline: 1.0644x; 1.0129x over previous
#include <cuda_runtime.h>
#include <cuda_bf16.h>
#include <math.h>
#include <stdint.h>

#define N_NODES 50000
#define N_EDGES 800000
#define ET (N_EDGES + N_NODES)
#define D 128
#define BQ 1024
#define H3 384
#define EPSV 1e-5f
#define NT_TILES 391             // ceil(50000/128)
#define NB_SCAN 196              // ceil(50000/256)

#define NEG_INF (__int_as_float(0xff800000))

// ---------------- scratch (device globals; no allocation) ----------------
__device__ __nv_bfloat16 g_h16[(size_t)N_NODES * D];
__device__ float g_agg[N_NODES * D];
__device__ float g_hn[N_NODES * D];
__device__ float g_as[N_NODES];
__device__ float g_ad[N_NODES];
__device__ float g_e[ET];
__device__ float g_musum2[2 * D];
__device__ float g_varsum2[2 * D];
__device__ float g_z1[BQ * H3];
__device__ float g_lse[BQ];
__device__ float g_pmax[(size_t)BQ * NT_TILES];
__device__ float g_psum[(size_t)BQ * NT_TILES];
__device__ __nv_bfloat16 g_w16[(size_t)N_NODES * H3];
__device__ __nv_bfloat16 g_z16[BQ * H3];
// CSR
__device__ int g_deg[N_NODES];
__device__ int g_off[N_NODES + 1];
__device__ int g_cur[N_NODES];
__device__ int g_srcl[ET];
__device__ int g_bsum[NB_SCAN];
__device__ int g_boff[NB_SCAN];

// ================= CSR build =================
__global__ void k_zero_deg() {
    int i = blockIdx.x * blockDim.x + threadIdx.x;
    if (i < N_NODES) g_deg[i] = 0;
    if (i < 2 * D) { g_musum2[i] = 0.f; g_varsum2[i] = 0.f; }
}
__global__ void k_count(const int* __restrict__ ei) {
    int i = blockIdx.x * blockDim.x + threadIdx.x;
    if (i >= ET) return;
    int dst = (i < N_EDGES) ? ei[N_EDGES + i] : (i - N_EDGES);
    atomicAdd(&g_deg[dst], 1);
}
__global__ void k_bsums() {
    int tid = threadIdx.x;
    int i = blockIdx.x * 256 + tid;
    int v = (i < N_NODES) ? g_deg[i] : 0;
    int lane = tid & 31, wid = tid >> 5;
#pragma unroll
    for (int o = 16; o; o >>= 1) v += __shfl_down_sync(0xffffffff, v, o);
    __shared__ int ws[8];
    if (lane == 0) ws[wid] = v;
    __syncthreads();
    if (tid == 0) {
        int s = 0;
#pragma unroll
        for (int w = 0; w < 8; w++) s += ws[w];
        g_bsum[blockIdx.x] = s;
    }
}
__global__ void k_scan2() {
    int tid = threadIdx.x;
    int lane = tid & 31, wid = tid >> 5;
    int v = (tid < NB_SCAN) ? g_bsum[tid] : 0;
    int x = v;
#pragma unroll
    for (int o = 1; o < 32; o <<= 1) {
        int t = __shfl_up_sync(0xffffffff, x, o);
        if (lane >= o) x += t;
    }
    __shared__ int ws[8];
    if (lane == 31) ws[wid] = x;
    __syncthreads();
    if (wid == 0 && lane < 8) {
        int y = ws[lane];
#pragma unroll
        for (int o = 1; o < 8; o <<= 1) {
            int t = __shfl_up_sync(0xff, y, o);
            if (lane >= o) y += t;
        }
        ws[lane] = y;
    }
    __syncthreads();
    int prefix = wid ? ws[wid - 1] : 0;
    if (tid < NB_SCAN) g_boff[tid] = prefix + x - v;
}
__global__ void k_addback() {
    int tid = threadIdx.x;
    int i = blockIdx.x * 256 + tid;
    int v = (i < N_NODES) ? g_deg[i] : 0;
    int lane = tid & 31, wid = tid >> 5;
    int x = v;
#pragma unroll
    for (int o = 1; o < 32; o <<= 1) {
        int t = __shfl_up_sync(0xffffffff, x, o);
        if (lane >= o) x += t;
    }
    __shared__ int ws[8];
    if (lane == 31) ws[wid] = x;
    __syncthreads();
    if (wid == 0 && lane < 8) {
        int y = ws[lane];
#pragma unroll
        for (int o = 1; o < 8; o <<= 1) {
            int t = __shfl_up_sync(0xff, y, o);
            if (lane >= o) y += t;
        }
        ws[lane] = y;
    }
    __syncthreads();
    int prefix = (wid ? ws[wid - 1] : 0) + g_boff[blockIdx.x];
    int excl = prefix + x - v;
    if (i < N_NODES) { g_off[i] = excl; g_cur[i] = excl; }
    if (i == 0) g_off[N_NODES] = ET;
}
__global__ void k_fill(const int* __restrict__ ei) {
    int i = blockIdx.x * blockDim.x + threadIdx.x;
    if (i >= ET) return;
    int src, dst;
    if (i < N_EDGES) { src = ei[i]; dst = ei[N_EDGES + i]; }
    else { src = dst = i - N_EDGES; }
    int pos = atomicAdd(&g_cur[dst], 1);
    g_srcl[pos] = src;
}

// ================= weight conversion =================
__global__ void k_cvt_w(const float* __restrict__ W) {
    int i = blockIdx.x * blockDim.x + threadIdx.x;
    if (i >= N_NODES * H3 / 4) return;
    float4 v = ((const float4*)W)[i];
    __nv_bfloat162 lo = __floats2bfloat162_rn(v.x, v.y);
    __nv_bfloat162 hi = __floats2bfloat162_rn(v.z, v.w);
    ((__nv_bfloat162*)g_w16)[i * 2] = lo;
    ((__nv_bfloat162*)g_w16)[i * 2 + 1] = hi;
}

// ================= cp.async helpers =================
__device__ __forceinline__ void cp_async16(uint32_t saddr, const void* gptr, int srcBytes) {
    asm volatile("cp.async.cg.shared.global [%0], [%1], 16, %2;\n"
                 :: "r"(saddr), "l"(gptr), "r"(srcBytes));
}
__device__ __forceinline__ void cp_commit() {
    asm volatile("cp.async.commit_group;\n");
}
template <int NW>
__device__ __forceinline__ void cp_wait() {
    asm volatile("cp.async.wait_group %0;\n" :: "n"(NW));
}

// ================= mma wrappers =================
__device__ __forceinline__ void mma_tf32(float c[4], uint32_t a0, uint32_t a1,
                                         uint32_t a2, uint32_t a3,
                                         uint32_t b0, uint32_t b1) {
    asm volatile(
        "mma.sync.aligned.m16n8k8.row.col.f32.tf32.tf32.f32 "
        "{%0,%1,%2,%3}, {%4,%5,%6,%7}, {%8,%9}, {%0,%1,%2,%3};"
        : "+f"(c[0]), "+f"(c[1]), "+f"(c[2]), "+f"(c[3])
        : "r"(a0), "r"(a1), "r"(a2), "r"(a3), "r"(b0), "r"(b1));
}
__device__ __forceinline__ void mma_bf16(float c[4], uint32_t a0, uint32_t a1,
                                         uint32_t a2, uint32_t a3,
                                         uint32_t b0, uint32_t b1) {
    asm volatile(
        "mma.sync.aligned.m16n8k16.row.col.f32.bf16.bf16.f32 "
        "{%0,%1,%2,%3}, {%4,%5,%6,%7}, {%8,%9}, {%0,%1,%2,%3};"
        : "+f"(c[0]), "+f"(c[1]), "+f"(c[2]), "+f"(c[3])
        : "r"(a0), "r"(a1), "r"(a2), "r"(a3), "r"(b0), "r"(b1));
}

// ================= bf16 lin2 GEMM (single pass, fused LSE partials) =======
#define BPAD 72
#define BSTAGE (128 * BPAD)
#define LIN2_SMEM_B (4 * BSTAGE * 2)
__global__ __launch_bounds__(256) void k_mma_lin2(
    const float* __restrict__ bias, float* __restrict__ out)
{
    extern __shared__ __nv_bfloat16 smem16[];
    const int K = H3, Nn = N_NODES;
    __nv_bfloat16* Abuf = smem16;
    __nv_bfloat16* Bbuf = smem16 + 2 * BSTAGE;

    int tid = threadIdx.x;
    int warp = tid >> 5, lane = tid & 31;
    int wm = (warp & 1) * 64;
    int wnw = warp >> 1;
    int wn = wnw * 32;
    int bm = blockIdx.y * 128;
    int bn = blockIdx.x * 128;

    float c[4][4][4];
#pragma unroll
    for (int mt = 0; mt < 4; mt++)
#pragma unroll
        for (int nt = 0; nt < 4; nt++)
#pragma unroll
            for (int r = 0; r < 4; r++) c[mt][nt][r] = 0.f;

    int gr = lane >> 2, gc = lane & 3;

    auto load_tile = [&](int it, int stage) {
        int k0 = it * 64;
        __nv_bfloat16* Ad = Abuf + stage * BSTAGE;
        __nv_bfloat16* Bd = Bbuf + stage * BSTAGE;
#pragma unroll
        for (int l = 0; l < 4; l++) {
            int linear = tid + l * 256;
            int row = linear >> 3;
            int kc = (linear & 7) * 8;
            uint32_t sa = (uint32_t)__cvta_generic_to_shared(Ad + row * BPAD + kc);
            cp_async16(sa, g_z16 + (size_t)(bm + row) * K + k0 + kc, 16);
            int grow = bn + row;
            int ok = (grow < Nn);
            uint32_t sb = (uint32_t)__cvta_generic_to_shared(Bd + row * BPAD + kc);
            cp_async16(sb, g_w16 + (size_t)(ok ? grow : 0) * K + k0 + kc, ok ? 16 : 0);
        }
        cp_commit();
    };

    const int NIT = K / 64;
    load_tile(0, 0);
    for (int it = 0; it < NIT; it++) {
        int cur = it & 1;
        if (it + 1 < NIT) { load_tile(it + 1, cur ^ 1); cp_wait<1>(); }
        else cp_wait<0>();
        __syncthreads();

        const __nv_bfloat16* Ac = Abuf + cur * BSTAGE;
        const __nv_bfloat16* Bc = Bbuf + cur * BSTAGE;
#pragma unroll
        for (int ks = 0; ks < 4; ks++) {
            int kb = ks * 16;
            uint32_t a[4][4];
#pragma unroll
            for (int mt = 0; mt < 4; mt++) {
                int mrow = wm + mt * 16 + gr;
                a[mt][0] = *(const uint32_t*)&Ac[mrow * BPAD + kb + gc * 2];
                a[mt][1] = *(const uint32_t*)&Ac[(mrow + 8) * BPAD + kb + gc * 2];
                a[mt][2] = *(const uint32_t*)&Ac[mrow * BPAD + kb + 8 + gc * 2];
                a[mt][3] = *(const uint32_t*)&Ac[(mrow + 8) * BPAD + kb + 8 + gc * 2];
            }
            uint32_t b[4][2];
#pragma unroll
            for (int nt = 0; nt < 4; nt++) {
                int ncol = wn + nt * 8 + gr;
                b[nt][0] = *(const uint32_t*)&Bc[ncol * BPAD + kb + gc * 2];
                b[nt][1] = *(const uint32_t*)&Bc[ncol * BPAD + kb + 8 + gc * 2];
            }
#pragma unroll
            for (int mt = 0; mt < 4; mt++)
#pragma unroll
                for (int nt = 0; nt < 4; nt++)
                    mma_bf16(c[mt][nt], a[mt][0], a[mt][1], a[mt][2], a[mt][3],
                             b[nt][0], b[nt][1]);
        }
        __syncthreads();
    }

    float* smf   = (float*)smem16;
    float* sm_pm  = smf;
    float* sm_max = smf + 512;
    float* sm_ps  = smf + 512 + 128;

    int crow = lane >> 2, ccol = (lane & 3) * 2;
    float bv[4][2];
    bool ok[4][2];
#pragma unroll
    for (int nt = 0; nt < 4; nt++)
#pragma unroll
        for (int j = 0; j < 2; j++) {
            int col = bn + wn + nt * 8 + ccol + j;
            ok[nt][j] = (col < Nn);
            bv[nt][j] = ok[nt][j] ? bias[col] : 0.f;
        }

#pragma unroll
    for (int mt = 0; mt < 4; mt++) {
#pragma unroll
        for (int h = 0; h < 2; h++) {
            int lrow = wm + mt * 16 + crow + h * 8;
            int row = bm + lrow;
            float vmax = NEG_INF;
#pragma unroll
            for (int nt = 0; nt < 4; nt++)
#pragma unroll
                for (int j = 0; j < 2; j++) {
                    if (ok[nt][j]) {
                        float v = c[mt][nt][h * 2 + j] + bv[nt][j];
                        out[(size_t)row * Nn + (bn + wn + nt * 8 + ccol + j)] = v;
                        vmax = fmaxf(vmax, v);
                    }
                }
            vmax = fmaxf(vmax, __shfl_xor_sync(0xffffffff, vmax, 1));
            vmax = fmaxf(vmax, __shfl_xor_sync(0xffffffff, vmax, 2));
            if ((lane & 3) == 0) sm_pm[lrow * 4 + wnw] = vmax;
        }
    }
    __syncthreads();
    if (tid < 128) {
        float m = fmaxf(fmaxf(sm_pm[tid * 4], sm_pm[tid * 4 + 1]),
                        fmaxf(sm_pm[tid * 4 + 2], sm_pm[tid * 4 + 3]));
        sm_max[tid] = m;
    }
    __syncthreads();
#pragma unroll
    for (int mt = 0; mt < 4; mt++) {
#pragma unroll
        for (int h = 0; h < 2; h++) {
            int lrow = wm + mt * 16 + crow + h * 8;
            float M = sm_max[lrow];
            float ls = 0.f;
#pragma unroll
            for (int nt = 0; nt < 4; nt++)
#pragma unroll
                for (int j = 0; j < 2; j++)
                    if (ok[nt][j])
                        ls += __expf(c[mt][nt][h * 2 + j] + bv[nt][j] - M);
            ls += __shfl_xor_sync(0xffffffff, ls, 1);
            ls += __shfl_xor_sync(0xffffffff, ls, 2);
            if ((lane & 3) == 0) sm_ps[lrow * 4 + wnw] = ls;
        }
    }
    __syncthreads();
    if (tid < 128) {
        float s = sm_ps[tid * 4] + sm_ps[tid * 4 + 1] +
                  sm_ps[tid * 4 + 2] + sm_ps[tid * 4 + 3];
        g_pmax[(size_t)(bm + tid) * NT_TILES + blockIdx.x] = sm_max[tid];
        g_psum[(size_t)(bm + tid) * NT_TILES + blockIdx.x] = s;
    }
}

// ================= tf32 feature GEMM, fused attn dots, bf16 h output ======
#define MMA_PAD 36
#define MMA_STAGE_F (128 * MMA_PAD)
#define FEAT_SMEM_B (4 * MMA_STAGE_F * 4)
__global__ __launch_bounds__(256) void k_mma_feat(
    const float* __restrict__ Aext, const float* __restrict__ W,
    const float* __restrict__ asrc, const float* __restrict__ adst, int asel)
{
    extern __shared__ float smemf[];
    const float* A = asel ? g_hn : Aext;
    const int M = N_NODES, K = D;
    float* Abuf = smemf;
    float* Bbuf = smemf + 2 * MMA_STAGE_F;

    int tid = threadIdx.x;
    int warp = tid >> 5, lane = tid & 31;
    int wm = (warp & 1) * 64;
    int wnw = warp >> 1;
    int wn = wnw * 32;
    int bm = blockIdx.y * 128;

    float c[4][4][4];
#pragma unroll
    for (int mt = 0; mt < 4; mt++)
#pragma unroll
        for (int nt = 0; nt < 4; nt++)
#pragma unroll
            for (int r = 0; r < 4; r++) c[mt][nt][r] = 0.f;

    int gr = lane >> 2, gc = lane & 3;

    auto load_tile = [&](int it, int stage) {
        int k0 = it * 32;
        float* Ad = Abuf + stage * MMA_STAGE_F;
        float* Bd = Bbuf + stage * MMA_STAGE_F;
#pragma unroll
        for (int l = 0; l < 4; l++) {
            int linear = tid + l * 256;
            int row = linear >> 3;
            int kc = (linear & 7) * 4;
            int ar = bm + row;
            int okA = (ar < M);
            uint32_t sa = (uint32_t)__cvta_generic_to_shared(Ad + row * MMA_PAD + kc);
            cp_async16(sa, A + (size_t)(okA ? ar : 0) * K + k0 + kc, okA ? 16 : 0);
            uint32_t sbb = (uint32_t)__cvta_generic_to_shared(Bd + row * MMA_PAD + kc);
            cp_async16(sbb, W + (size_t)row * K + k0 + kc, 16);
        }
        cp_commit();
    };

    const int NIT = K / 32;
    load_tile(0, 0);
    for (int it = 0; it < NIT; it++) {
        int cur = it & 1;
        if (it + 1 < NIT) { load_tile(it + 1, cur ^ 1); cp_wait<1>(); }
        else cp_wait<0>();
        __syncthreads();

        const float* Ac = Abuf + cur * MMA_STAGE_F;
        const float* Bc = Bbuf + cur * MMA_STAGE_F;
#pragma unroll
        for (int ks = 0; ks < 4; ks++) {
            int kb = ks * 8;
            uint32_t a[4][4];
#pragma unroll
            for (int mt = 0; mt < 4; mt++) {
                int mrow = wm + mt * 16 + gr;
                a[mt][0] = __float_as_uint(Ac[mrow * MMA_PAD + kb + gc]);
                a[mt][1] = __float_as_uint(Ac[(mrow + 8) * MMA_PAD + kb + gc]);
                a[mt][2] = __float_as_uint(Ac[mrow * MMA_PAD + kb + gc + 4]);
                a[mt][3] = __float_as_uint(Ac[(mrow + 8) * MMA_PAD + kb + gc + 4]);
            }
            uint32_t b[4][2];
#pragma unroll
            for (int nt = 0; nt < 4; nt++) {
                int ncol = wn + nt * 8 + gr;
                b[nt][0] = __float_as_uint(Bc[ncol * MMA_PAD + kb + gc]);
                b[nt][1] = __float_as_uint(Bc[ncol * MMA_PAD + kb + gc + 4]);
            }
#pragma unroll
            for (int mt = 0; mt < 4; mt++)
#pragma unroll
                for (int nt = 0; nt < 4; nt++)
                    mma_tf32(c[mt][nt], a[mt][0], a[mt][1], a[mt][2], a[mt][3],
                             b[nt][0], b[nt][1]);
        }
        __syncthreads();
    }

    float* sm_as = smemf;
    float* sm_ad = smemf + 512;

    int crow = lane >> 2, ccol = (lane & 3) * 2;
    float av[4][2], dv[4][2];
#pragma unroll
    for (int nt = 0; nt < 4; nt++)
#pragma unroll
        for (int j = 0; j < 2; j++) {
            int col = wn + nt * 8 + ccol + j;
            av[nt][j] = asrc[col];
            dv[nt][j] = adst[col];
        }

#pragma unroll
    for (int mt = 0; mt < 4; mt++) {
#pragma unroll
        for (int h = 0; h < 2; h++) {
            int lrow = wm + mt * 16 + crow + h * 8;
            int row = bm + lrow;
            float pas = 0.f, pad = 0.f;
            if (row < M) {
#pragma unroll
                for (int nt = 0; nt < 4; nt++) {
                    float v0 = c[mt][nt][h * 2];
                    float v1 = c[mt][nt][h * 2 + 1];
                    int col = wn + nt * 8 + ccol;
                    *(__nv_bfloat162*)(g_h16 + (size_t)row * D + col) =
                        __floats2bfloat162_rn(v0, v1);
                    pas += v0 * av[nt][0] + v1 * av[nt][1];
                    pad += v0 * dv[nt][0] + v1 * dv[nt][1];
                }
            }
            pas += __shfl_xor_sync(0xffffffff, pas, 1);
            pas += __shfl_xor_sync(0xffffffff, pas, 2);
            pad += __shfl_xor_sync(0xffffffff, pad, 1);
            pad += __shfl_xor_sync(0xffffffff, pad, 2);
            if ((lane & 3) == 0) {
                sm_as[lrow * 4 + wnw] = pas;
                sm_ad[lrow * 4 + wnw] = pad;
            }
        }
    }
    __syncthreads();
    if (tid < 128) {
        int row = bm + tid;
        if (row < M) {
            g_as[row] = sm_as[tid * 4] + sm_as[tid * 4 + 1] +
                        sm_as[tid * 4 + 2] + sm_as[tid * 4 + 3];
            g_ad[row] = sm_ad[tid * 4] + sm_ad[tid * 4 + 1] +
                        sm_ad[tid * 4 + 2] + sm_ad[tid * 4 + 3];
        }
    }
}

// ================= fp32 SGEMM lin1 with fused gather =================
__global__ __launch_bounds__(256) void k_sgemm_lin1(
    const int* __restrict__ x, const float* __restrict__ Bm,
    const float* __restrict__ bias)
{
    const int Nn = H3, K = H3;
    float* C = g_z1;

    __shared__ float As[8][128];
    __shared__ float Bs[8][128];

    int tid = threadIdx.x;
    int tx = tid & 15, ty = tid >> 4;
    int bm = blockIdx.y * 128, bn = blockIdx.x * 128;

    float acc[8][8];
#pragma unroll
    for (int i = 0; i < 8; i++)
#pragma unroll
        for (int j = 0; j < 8; j++) acc[i][j] = 0.f;

    int lr = tid >> 1;
    int lk = (tid & 1) * 4;

    for (int k0 = 0; k0 < K; k0 += 8) {
        int ar = bm + lr;
        int kidx = k0 + lk;
        int node = x[ar * 3 + (kidx >> 7)];
        float4 a4 = *(const float4*)(g_hn + (size_t)node * D + (kidx & 127));
        As[lk + 0][lr] = a4.x; As[lk + 1][lr] = a4.y;
        As[lk + 2][lr] = a4.z; As[lk + 3][lr] = a4.w;

        float4 b4 = make_float4(0.f, 0.f, 0.f, 0.f);
        int br = bn + lr;
        if (br < Nn) b4 = *(const float4*)(Bm + (size_t)br * K + kidx);
        Bs[lk + 0][lr] = b4.x; Bs[lk + 1][lr] = b4.y;
        Bs[lk + 2][lr] = b4.z; Bs[lk + 3][lr] = b4.w;
        __syncthreads();

#pragma unroll
        for (int k = 0; k < 8; k++) {
            float4 a0 = *(const float4*)&As[k][ty * 8];
            float4 a1 = *(const float4*)&As[k][ty * 8 + 4];
            float4 b0 = *(const float4*)&Bs[k][tx * 8];
            float4 b1 = *(const float4*)&Bs[k][tx * 8 + 4];
            float a[8] = {a0.x, a0.y, a0.z, a0.w, a1.x, a1.y, a1.z, a1.w};
            float b[8] = {b0.x, b0.y, b0.z, b0.w, b1.x, b1.y, b1.z, b1.w};
#pragma unroll
            for (int i = 0; i < 8; i++)
#pragma unroll
                for (int j = 0; j < 8; j++) acc[i][j] += a[i] * b[j];
        }
        __syncthreads();
    }

#pragma unroll
    for (int i = 0; i < 8; i++) {
        int row = bm + ty * 8 + i;
#pragma unroll
        for (int j = 0; j < 8; j++) {
            int col = bn + tx * 8 + j;
            if (col < Nn) C[(size_t)row * Nn + col] = acc[i][j] + bias[col];
        }
    }
}

// ================= LSE merge + subtract =================
__global__ void k_reduce_lse() {
    int row = blockIdx.x * 8 + (threadIdx.x >> 5);
    int lane = threadIdx.x & 31;
    const float* pm = g_pmax + (size_t)row * NT_TILES;
    const float* ps = g_psum + (size_t)row * NT_TILES;
    float M = NEG_INF;
    for (int i = lane; i < NT_TILES; i += 32) M = fmaxf(M, pm[i]);
#pragma unroll
    for (int o = 16; o; o >>= 1) M = fmaxf(M, __shfl_xor_sync(0xffffffff, M, o));
    float S = 0.f;
    for (int i = lane; i < NT_TILES; i += 32) S += ps[i] * __expf(pm[i] - M);
#pragma unroll
    for (int o = 16; o; o >>= 1) S += __shfl_xor_sync(0xffffffff, S, o);
    if (lane == 0) g_lse[row] = M + logf(S);
}

__global__ void k_sub_lse(float* __restrict__ out) {
    int idx = blockIdx.x * blockDim.x + threadIdx.x;
    if (idx >= BQ * 12500) return;
    int row = idx / 12500;
    float l = g_lse[row];
    float4* p = (float4*)out + idx;
    float4 v = *p;
    v.x -= l; v.y -= l; v.z -= l; v.w -= l;
    *p = v;
}

// ================= per-node attention aggregate (fused expsum) ============
__global__ void k_node_attagg() {
    int gt = blockIdx.x * blockDim.x + threadIdx.x;
    int node = gt >> 5, lane = gt & 31;
    if (node >= N_NODES) return;
    int beg = g_off[node], end = g_off[node + 1];
    float ad = g_ad[node];

    float m = NEG_INF;
    for (int i = beg + lane; i < end; i += 32) {
        float s = g_as[g_srcl[i]] + ad;
        float e = (s > 0.f) ? s : 0.2f * s;
        g_e[i] = e;
        m = fmaxf(m, e);
    }
#pragma unroll
    for (int o = 16; o; o >>= 1) m = fmaxf(m, __shfl_xor_sync(0xffffffff, m, o));
    __syncwarp();

    float4 acc = make_float4(0.f, 0.f, 0.f, 0.f);
    float den = 0.f;
    int coff = lane * 4;
    int i = beg;
    for (; i + 3 < end; i += 4) {
        float w0 = __expf(g_e[i] - m),     w1 = __expf(g_e[i + 1] - m);
        float w2 = __expf(g_e[i + 2] - m), w3 = __expf(g_e[i + 3] - m);
        den += (w0 + w1) + (w2 + w3);
        int s0 = g_srcl[i],     s1 = g_srcl[i + 1];
        int s2 = g_srcl[i + 2], s3 = g_srcl[i + 3];
        uint2 p0 = *(const uint2*)(g_h16 + (size_t)s0 * D + coff);
        uint2 p1 = *(const uint2*)(g_h16 + (size_t)s1 * D + coff);
        uint2 p2 = *(const uint2*)(g_h16 + (size_t)s2 * D + coff);
        uint2 p3 = *(const uint2*)(g_h16 + (size_t)s3 * D + coff);
        float2 a0 = __bfloat1622float2(*(__nv_bfloat162*)&p0.x);
        float2 b0 = __bfloat1622float2(*(__nv_bfloat162*)&p0.y);
        float2 a1 = __bfloat1622float2(*(__nv_bfloat162*)&p1.x);
        float2 b1 = __bfloat1622float2(*(__nv_bfloat162*)&p1.y);
        float2 a2 = __bfloat1622float2(*(__nv_bfloat162*)&p2.x);
        float2 b2 = __bfloat1622float2(*(__nv_bfloat162*)&p2.y);
        float2 a3 = __bfloat1622float2(*(__nv_bfloat162*)&p3.x);
        float2 b3 = __bfloat1622float2(*(__nv_bfloat162*)&p3.y);
        acc.x += w0 * a0.x + w1 * a1.x + w2 * a2.x + w3 * a3.x;
        acc.y += w0 * a0.y + w1 * a1.y + w2 * a2.y + w3 * a3.y;
        acc.z += w0 * b0.x + w1 * b1.x + w2 * b2.x + w3 * b3.x;
        acc.w += w0 * b0.y + w1 * b1.y + w2 * b2.y + w3 * b3.y;
    }
    for (; i < end; i++) {
        float w = __expf(g_e[i] - m);
        den += w;
        int s = g_srcl[i];
        uint2 p = *(const uint2*)(g_h16 + (size_t)s * D + coff);
        float2 a = __bfloat1622float2(*(__nv_bfloat162*)&p.x);
        float2 b = __bfloat1622float2(*(__nv_bfloat162*)&p.y);
        acc.x += w * a.x; acc.y += w * a.y;
        acc.z += w * b.x; acc.w += w * b.y;
    }
    float inv = 1.f / den;
    acc.x *= inv; acc.y *= inv; acc.z *= inv; acc.w *= inv;
    *(float4*)(g_agg + (size_t)node * D + coff) = acc;
}

// ================= GraphNorm =================
#define RPB 64
__global__ void k_colstats(int layer) {
    int col = threadIdx.x;
    int r0 = blockIdx.x * RPB;
    int r1 = min(r0 + RPB, N_NODES);
    float s = 0.f, s2 = 0.f;
    for (int r = r0; r < r1; r++) {
        float a = g_agg[(size_t)r * D + col];
        s += a; s2 += a * a;
    }
    atomicAdd(&g_musum2[layer * D + col], s);
    atomicAdd(&g_varsum2[layer * D + col], s2);
}
__global__ void k_normalize(const float* __restrict__ bb, const float* __restrict__ gw,
                            const float* __restrict__ gb, const float* __restrict__ ms,
                            int layer) {
    int idx = blockIdx.x * blockDim.x + threadIdx.x;
    if (idx >= N_NODES * D) return;
    int d = idx & (D - 1);
    float S1 = g_musum2[layer * D + d] * (1.f / N_NODES);
    float S2 = g_varsum2[layer * D + d] * (1.f / N_NODES);
    float bv = bb[d];
    float mu = S1 + bv;
    float cc = bv - mu * ms[d];
    float var = S2 + 2.f * cc * S1 + cc * cc;
    float istd = rsqrtf(var + EPSV);
    float t = g_agg[idx] + cc;
    float v = t * istd * gw[d] + gb[d];
    g_hn[idx] = v > 0.f ? v : 0.f;
}

// ================= head BN =================
__global__ void k_bn_relu(const float* __restrict__ bw, const float* __restrict__ bb) {
    int c = blockIdx.x;
    int t = threadIdx.x;
    __shared__ float sm[256], ss[256];
    float s = 0.f, s2 = 0.f;
    for (int r = t; r < BQ; r += 256) {
        float v = g_z1[r * H3 + c];
        s += v; s2 += v * v;
    }
    sm[t] = s; ss[t] = s2;
    __syncthreads();
    for (int o = 128; o; o >>= 1) {
        if (t < o) { sm[t] += sm[t + o]; ss[t] += ss[t + o]; }
        __syncthreads();
    }
    float mu = sm[0] * (1.f / BQ);
    float var = ss[0] * (1.f / BQ) - mu * mu;
    float istd = rsqrtf(var + EPSV);
    float w = bw[c], bias = bb[c];
    for (int r = t; r < BQ; r += 256) {
        float v = (g_z1[r * H3 + c] - mu) * istd * w + bias;
        g_z16[r * H3 + c] = __float2bfloat16(v > 0.f ? v : 0.f);
    }
}

// ================= host driver =================
extern "C" void kernel_launch(void* const* d_in, const int* in_sizes, int n_in,
                              void* d_out, int out_size)
{
    const int*   x       = (const int*)  d_in[0];
    const int*   ei      = (const int*)  d_in[1];
    const float* emb     = (const float*)d_in[2];
    const float* W1      = (const float*)d_in[3];
    const float* asrc1   = (const float*)d_in[4];
    const float* adst1   = (const float*)d_in[5];
    const float* b1      = (const float*)d_in[6];
    const float* gn1w    = (const float*)d_in[7];
    const float* gn1b    = (const float*)d_in[8];
    const float* gn1ms   = (const float*)d_in[9];
    const float* W2      = (const float*)d_in[10];
    const float* asrc2   = (const float*)d_in[11];
    const float* adst2   = (const float*)d_in[12];
    const float* b2      = (const float*)d_in[13];
    const float* gn2w    = (const float*)d_in[14];
    const float* gn2b    = (const float*)d_in[15];
    const float* gn2ms   = (const float*)d_in[16];
    const float* lin1W   = (const float*)d_in[17];
    const float* lin1b   = (const float*)d_in[18];
    const float* bnw     = (const float*)d_in[19];
    const float* bnb     = (const float*)d_in[20];
    const float* lin2W   = (const float*)d_in[21];
    const float* lin2b   = (const float*)d_in[22];
    float* out = (float*)d_out;

    // one-time resource init (first call is the uncaptured correctness run)
    static cudaStream_t s_b = nullptr;
    static cudaEvent_t ev_fork = nullptr, ev_join = nullptr;
    if (s_b == nullptr) {
        cudaStreamCreateWithFlags(&s_b, cudaStreamNonBlocking);
        cudaEventCreateWithFlags(&ev_fork, cudaEventDisableTiming);
        cudaEventCreateWithFlags(&ev_join, cudaEventDisableTiming);
        cudaFuncSetAttribute(k_mma_lin2, cudaFuncAttributeMaxDynamicSharedMemorySize, LIN2_SMEM_B);
        cudaFuncSetAttribute(k_mma_feat, cudaFuncAttributeMaxDynamicSharedMemorySize, FEAT_SMEM_B);
    }

    dim3 gf(1, NT_TILES);

    // ---- fork: stream B does cvt_w + feat layer-1; main stream does CSR ----
    cudaEventRecord(ev_fork, 0);
    cudaStreamWaitEvent(s_b, ev_fork, 0);

    k_cvt_w<<<(N_NODES * H3 / 4 + 255) / 256, 256, 0, s_b>>>(lin2W);
    k_mma_feat<<<gf, 256, FEAT_SMEM_B, s_b>>>(emb, W1, asrc1, adst1, 0);
    cudaEventRecord(ev_join, s_b);

    k_zero_deg<<<(N_NODES + 255) / 256, 256>>>();
    k_count<<<(ET + 255) / 256, 256>>>(ei);
    k_bsums<<<NB_SCAN, 256>>>();
    k_scan2<<<1, 256>>>();
    k_addback<<<NB_SCAN, 256>>>();
    k_fill<<<(ET + 255) / 256, 256>>>(ei);

    cudaStreamWaitEvent(0, ev_join, 0);
    // ---- join ----

    // --- layer 1 rest ---
    k_node_attagg<<<(N_NODES * 32 + 255) / 256, 256>>>();
    k_colstats<<<(N_NODES + RPB - 1) / RPB, D>>>(0);
    k_normalize<<<(N_NODES * D + 255) / 256, 256>>>(b1, gn1w, gn1b, gn1ms, 0);

    // --- layer 2 ---
    k_mma_feat<<<gf, 256, FEAT_SMEM_B>>>(nullptr, W2, asrc2, adst2, 1);
    k_node_attagg<<<(N_NODES * 32 + 255) / 256, 256>>>();
    k_colstats<<<(N_NODES + RPB - 1) / RPB, D>>>(1);
    k_normalize<<<(N_NODES * D + 255) / 256, 256>>>(b2, gn2w, gn2b, gn2ms, 1);

    // --- head ---
    dim3 gz1((H3 + 127) / 128, BQ / 128);
    k_sgemm_lin1<<<gz1, 256>>>(x, lin1W, lin1b);
    k_bn_relu<<<H3, 256>>>(bnw, bnb);
    dim3 gz2(NT_TILES, BQ / 128);
    k_mma_lin2<<<gz2, 256, LIN2_SMEM_B>>>(lin2b, out);
    k_reduce_lse<<<BQ / 8, 256>>>();
    k_sub_lse<<<(BQ * 12500 + 255) / 256, 256>>>(out);
}

// round 16
// speedup vs baseline: 1.0905x; 1.0245x over previous
#include <cuda_runtime.h>
#include <cuda_bf16.h>
#include <math.h>
#include <stdint.h>

#define N_NODES 50000
#define N_EDGES 800000
#define ET (N_EDGES + N_NODES)
#define D 128
#define BQ 1024
#define H3 384
#define EPSV 1e-5f
#define NT_TILES 391             // ceil(50000/128)
#define NB_SCAN 196              // ceil(50000/256)

#define NEG_INF (__int_as_float(0xff800000))

// ---------------- scratch (device globals; no allocation) ----------------
__device__ __nv_bfloat16 g_h16[(size_t)N_NODES * D];
__device__ float g_agg[N_NODES * D];
__device__ float g_hn[N_NODES * D];
__device__ float g_as[N_NODES];
__device__ float g_ad[N_NODES];
__device__ float g_e[ET];
__device__ float g_musum2[2 * D];
__device__ float g_varsum2[2 * D];
__device__ float g_z1[BQ * H3];
__device__ float g_pmax[(size_t)BQ * NT_TILES];
__device__ float g_psum[(size_t)BQ * NT_TILES];
__device__ __nv_bfloat16 g_w16[(size_t)N_NODES * H3];
__device__ __nv_bfloat16 g_z16[BQ * H3];
// CSR
__device__ int g_deg[N_NODES];
__device__ int g_off[N_NODES + 1];
__device__ int g_cur[N_NODES];
__device__ int g_srcl[ET];
__device__ int g_bsum[NB_SCAN];
__device__ int g_boff[NB_SCAN];

// ================= CSR build =================
__global__ void k_zero_deg() {
    int i = blockIdx.x * blockDim.x + threadIdx.x;
    if (i < N_NODES) g_deg[i] = 0;
    if (i < 2 * D) { g_musum2[i] = 0.f; g_varsum2[i] = 0.f; }
}
__global__ void k_count(const int* __restrict__ ei) {
    int i = blockIdx.x * blockDim.x + threadIdx.x;
    if (i >= ET) return;
    int dst = (i < N_EDGES) ? ei[N_EDGES + i] : (i - N_EDGES);
    atomicAdd(&g_deg[dst], 1);
}
__global__ void k_bsums() {
    int tid = threadIdx.x;
    int i = blockIdx.x * 256 + tid;
    int v = (i < N_NODES) ? g_deg[i] : 0;
    int lane = tid & 31, wid = tid >> 5;
#pragma unroll
    for (int o = 16; o; o >>= 1) v += __shfl_down_sync(0xffffffff, v, o);
    __shared__ int ws[8];
    if (lane == 0) ws[wid] = v;
    __syncthreads();
    if (tid == 0) {
        int s = 0;
#pragma unroll
        for (int w = 0; w < 8; w++) s += ws[w];
        g_bsum[blockIdx.x] = s;
    }
}
__global__ void k_scan2() {
    int tid = threadIdx.x;
    int lane = tid & 31, wid = tid >> 5;
    int v = (tid < NB_SCAN) ? g_bsum[tid] : 0;
    int x = v;
#pragma unroll
    for (int o = 1; o < 32; o <<= 1) {
        int t = __shfl_up_sync(0xffffffff, x, o);
        if (lane >= o) x += t;
    }
    __shared__ int ws[8];
    if (lane == 31) ws[wid] = x;
    __syncthreads();
    if (wid == 0 && lane < 8) {
        int y = ws[lane];
#pragma unroll
        for (int o = 1; o < 8; o <<= 1) {
            int t = __shfl_up_sync(0xff, y, o);
            if (lane >= o) y += t;
        }
        ws[lane] = y;
    }
    __syncthreads();
    int prefix = wid ? ws[wid - 1] : 0;
    if (tid < NB_SCAN) g_boff[tid] = prefix + x - v;
}
__global__ void k_addback() {
    int tid = threadIdx.x;
    int i = blockIdx.x * 256 + tid;
    int v = (i < N_NODES) ? g_deg[i] : 0;
    int lane = tid & 31, wid = tid >> 5;
    int x = v;
#pragma unroll
    for (int o = 1; o < 32; o <<= 1) {
        int t = __shfl_up_sync(0xffffffff, x, o);
        if (lane >= o) x += t;
    }
    __shared__ int ws[8];
    if (lane == 31) ws[wid] = x;
    __syncthreads();
    if (wid == 0 && lane < 8) {
        int y = ws[lane];
#pragma unroll
        for (int o = 1; o < 8; o <<= 1) {
            int t = __shfl_up_sync(0xff, y, o);
            if (lane >= o) y += t;
        }
        ws[lane] = y;
    }
    __syncthreads();
    int prefix = (wid ? ws[wid - 1] : 0) + g_boff[blockIdx.x];
    int excl = prefix + x - v;
    if (i < N_NODES) { g_off[i] = excl; g_cur[i] = excl; }
    if (i == 0) g_off[N_NODES] = ET;
}
__global__ void k_fill(const int* __restrict__ ei) {
    int i = blockIdx.x * blockDim.x + threadIdx.x;
    if (i >= ET) return;
    int src, dst;
    if (i < N_EDGES) { src = ei[i]; dst = ei[N_EDGES + i]; }
    else { src = dst = i - N_EDGES; }
    int pos = atomicAdd(&g_cur[dst], 1);
    g_srcl[pos] = src;
}

// ================= weight conversion =================
__global__ void k_cvt_w(const float* __restrict__ W) {
    int i = blockIdx.x * blockDim.x + threadIdx.x;
    if (i >= N_NODES * H3 / 4) return;
    float4 v = ((const float4*)W)[i];
    __nv_bfloat162 lo = __floats2bfloat162_rn(v.x, v.y);
    __nv_bfloat162 hi = __floats2bfloat162_rn(v.z, v.w);
    ((__nv_bfloat162*)g_w16)[i * 2] = lo;
    ((__nv_bfloat162*)g_w16)[i * 2 + 1] = hi;
}

// ================= cp.async helpers =================
__device__ __forceinline__ void cp_async16(uint32_t saddr, const void* gptr, int srcBytes) {
    asm volatile("cp.async.cg.shared.global [%0], [%1], 16, %2;\n"
                 :: "r"(saddr), "l"(gptr), "r"(srcBytes));
}
__device__ __forceinline__ void cp_commit() {
    asm volatile("cp.async.commit_group;\n");
}
template <int NW>
__device__ __forceinline__ void cp_wait() {
    asm volatile("cp.async.wait_group %0;\n" :: "n"(NW));
}

// ================= mma wrappers =================
__device__ __forceinline__ void mma_tf32(float c[4], uint32_t a0, uint32_t a1,
                                         uint32_t a2, uint32_t a3,
                                         uint32_t b0, uint32_t b1) {
    asm volatile(
        "mma.sync.aligned.m16n8k8.row.col.f32.tf32.tf32.f32 "
        "{%0,%1,%2,%3}, {%4,%5,%6,%7}, {%8,%9}, {%0,%1,%2,%3};"
        : "+f"(c[0]), "+f"(c[1]), "+f"(c[2]), "+f"(c[3])
        : "r"(a0), "r"(a1), "r"(a2), "r"(a3), "r"(b0), "r"(b1));
}
__device__ __forceinline__ void mma_bf16(float c[4], uint32_t a0, uint32_t a1,
                                         uint32_t a2, uint32_t a3,
                                         uint32_t b0, uint32_t b1) {
    asm volatile(
        "mma.sync.aligned.m16n8k16.row.col.f32.bf16.bf16.f32 "
        "{%0,%1,%2,%3}, {%4,%5,%6,%7}, {%8,%9}, {%0,%1,%2,%3};"
        : "+f"(c[0]), "+f"(c[1]), "+f"(c[2]), "+f"(c[3])
        : "r"(a0), "r"(a1), "r"(a2), "r"(a3), "r"(b0), "r"(b1));
}

// ================= bf16 lin2 GEMM (single pass, fused LSE partials) =======
#define BPAD 72
#define BSTAGE (128 * BPAD)
#define LIN2_SMEM_B (4 * BSTAGE * 2)
__global__ __launch_bounds__(256) void k_mma_lin2(
    const float* __restrict__ bias, float* __restrict__ out)
{
    extern __shared__ __nv_bfloat16 smem16[];
    const int K = H3, Nn = N_NODES;
    __nv_bfloat16* Abuf = smem16;
    __nv_bfloat16* Bbuf = smem16 + 2 * BSTAGE;

    int tid = threadIdx.x;
    int warp = tid >> 5, lane = tid & 31;
    int wm = (warp & 1) * 64;
    int wnw = warp >> 1;
    int wn = wnw * 32;
    int bm = blockIdx.y * 128;
    int bn = blockIdx.x * 128;

    float c[4][4][4];
#pragma unroll
    for (int mt = 0; mt < 4; mt++)
#pragma unroll
        for (int nt = 0; nt < 4; nt++)
#pragma unroll
            for (int r = 0; r < 4; r++) c[mt][nt][r] = 0.f;

    int gr = lane >> 2, gc = lane & 3;

    auto load_tile = [&](int it, int stage) {
        int k0 = it * 64;
        __nv_bfloat16* Ad = Abuf + stage * BSTAGE;
        __nv_bfloat16* Bd = Bbuf + stage * BSTAGE;
#pragma unroll
        for (int l = 0; l < 4; l++) {
            int linear = tid + l * 256;
            int row = linear >> 3;
            int kc = (linear & 7) * 8;
            uint32_t sa = (uint32_t)__cvta_generic_to_shared(Ad + row * BPAD + kc);
            cp_async16(sa, g_z16 + (size_t)(bm + row) * K + k0 + kc, 16);
            int grow = bn + row;
            int ok = (grow < Nn);
            uint32_t sb = (uint32_t)__cvta_generic_to_shared(Bd + row * BPAD + kc);
            cp_async16(sb, g_w16 + (size_t)(ok ? grow : 0) * K + k0 + kc, ok ? 16 : 0);
        }
        cp_commit();
    };

    const int NIT = K / 64;
    load_tile(0, 0);
    for (int it = 0; it < NIT; it++) {
        int cur = it & 1;
        if (it + 1 < NIT) { load_tile(it + 1, cur ^ 1); cp_wait<1>(); }
        else cp_wait<0>();
        __syncthreads();

        const __nv_bfloat16* Ac = Abuf + cur * BSTAGE;
        const __nv_bfloat16* Bc = Bbuf + cur * BSTAGE;
#pragma unroll
        for (int ks = 0; ks < 4; ks++) {
            int kb = ks * 16;
            uint32_t a[4][4];
#pragma unroll
            for (int mt = 0; mt < 4; mt++) {
                int mrow = wm + mt * 16 + gr;
                a[mt][0] = *(const uint32_t*)&Ac[mrow * BPAD + kb + gc * 2];
                a[mt][1] = *(const uint32_t*)&Ac[(mrow + 8) * BPAD + kb + gc * 2];
                a[mt][2] = *(const uint32_t*)&Ac[mrow * BPAD + kb + 8 + gc * 2];
                a[mt][3] = *(const uint32_t*)&Ac[(mrow + 8) * BPAD + kb + 8 + gc * 2];
            }
            uint32_t b[4][2];
#pragma unroll
            for (int nt = 0; nt < 4; nt++) {
                int ncol = wn + nt * 8 + gr;
                b[nt][0] = *(const uint32_t*)&Bc[ncol * BPAD + kb + gc * 2];
                b[nt][1] = *(const uint32_t*)&Bc[ncol * BPAD + kb + 8 + gc * 2];
            }
#pragma unroll
            for (int mt = 0; mt < 4; mt++)
#pragma unroll
                for (int nt = 0; nt < 4; nt++)
                    mma_bf16(c[mt][nt], a[mt][0], a[mt][1], a[mt][2], a[mt][3],
                             b[nt][0], b[nt][1]);
        }
        __syncthreads();
    }

    float* smf   = (float*)smem16;
    float* sm_pm  = smf;
    float* sm_max = smf + 512;
    float* sm_ps  = smf + 512 + 128;

    int crow = lane >> 2, ccol = (lane & 3) * 2;
    float bv[4][2];
    bool ok[4][2];
#pragma unroll
    for (int nt = 0; nt < 4; nt++)
#pragma unroll
        for (int j = 0; j < 2; j++) {
            int col = bn + wn + nt * 8 + ccol + j;
            ok[nt][j] = (col < Nn);
            bv[nt][j] = ok[nt][j] ? bias[col] : 0.f;
        }

#pragma unroll
    for (int mt = 0; mt < 4; mt++) {
#pragma unroll
        for (int h = 0; h < 2; h++) {
            int lrow = wm + mt * 16 + crow + h * 8;
            int row = bm + lrow;
            float vmax = NEG_INF;
#pragma unroll
            for (int nt = 0; nt < 4; nt++)
#pragma unroll
                for (int j = 0; j < 2; j++) {
                    if (ok[nt][j]) {
                        float v = c[mt][nt][h * 2 + j] + bv[nt][j];
                        out[(size_t)row * Nn + (bn + wn + nt * 8 + ccol + j)] = v;
                        vmax = fmaxf(vmax, v);
                    }
                }
            vmax = fmaxf(vmax, __shfl_xor_sync(0xffffffff, vmax, 1));
            vmax = fmaxf(vmax, __shfl_xor_sync(0xffffffff, vmax, 2));
            if ((lane & 3) == 0) sm_pm[lrow * 4 + wnw] = vmax;
        }
    }
    __syncthreads();
    if (tid < 128) {
        float m = fmaxf(fmaxf(sm_pm[tid * 4], sm_pm[tid * 4 + 1]),
                        fmaxf(sm_pm[tid * 4 + 2], sm_pm[tid * 4 + 3]));
        sm_max[tid] = m;
    }
    __syncthreads();
#pragma unroll
    for (int mt = 0; mt < 4; mt++) {
#pragma unroll
        for (int h = 0; h < 2; h++) {
            int lrow = wm + mt * 16 + crow + h * 8;
            float M = sm_max[lrow];
            float ls = 0.f;
#pragma unroll
            for (int nt = 0; nt < 4; nt++)
#pragma unroll
                for (int j = 0; j < 2; j++)
                    if (ok[nt][j])
                        ls += __expf(c[mt][nt][h * 2 + j] + bv[nt][j] - M);
            ls += __shfl_xor_sync(0xffffffff, ls, 1);
            ls += __shfl_xor_sync(0xffffffff, ls, 2);
            if ((lane & 3) == 0) sm_ps[lrow * 4 + wnw] = ls;
        }
    }
    __syncthreads();
    if (tid < 128) {
        float s = sm_ps[tid * 4] + sm_ps[tid * 4 + 1] +
                  sm_ps[tid * 4 + 2] + sm_ps[tid * 4 + 3];
        g_pmax[(size_t)(bm + tid) * NT_TILES + blockIdx.x] = sm_max[tid];
        g_psum[(size_t)(bm + tid) * NT_TILES + blockIdx.x] = s;
    }
}

// ================= tf32 feature GEMM, fused attn dots, bf16 h output ======
#define MMA_PAD 36
#define MMA_STAGE_F (128 * MMA_PAD)
#define FEAT_SMEM_B (4 * MMA_STAGE_F * 4)
__global__ __launch_bounds__(256) void k_mma_feat(
    const float* __restrict__ Aext, const float* __restrict__ W,
    const float* __restrict__ asrc, const float* __restrict__ adst, int asel)
{
    extern __shared__ float smemf[];
    const float* A = asel ? g_hn : Aext;
    const int M = N_NODES, K = D;
    float* Abuf = smemf;
    float* Bbuf = smemf + 2 * MMA_STAGE_F;

    int tid = threadIdx.x;
    int warp = tid >> 5, lane = tid & 31;
    int wm = (warp & 1) * 64;
    int wnw = warp >> 1;
    int wn = wnw * 32;
    int bm = blockIdx.y * 128;

    float c[4][4][4];
#pragma unroll
    for (int mt = 0; mt < 4; mt++)
#pragma unroll
        for (int nt = 0; nt < 4; nt++)
#pragma unroll
            for (int r = 0; r < 4; r++) c[mt][nt][r] = 0.f;

    int gr = lane >> 2, gc = lane & 3;

    auto load_tile = [&](int it, int stage) {
        int k0 = it * 32;
        float* Ad = Abuf + stage * MMA_STAGE_F;
        float* Bd = Bbuf + stage * MMA_STAGE_F;
#pragma unroll
        for (int l = 0; l < 4; l++) {
            int linear = tid + l * 256;
            int row = linear >> 3;
            int kc = (linear & 7) * 4;
            int ar = bm + row;
            int okA = (ar < M);
            uint32_t sa = (uint32_t)__cvta_generic_to_shared(Ad + row * MMA_PAD + kc);
            cp_async16(sa, A + (size_t)(okA ? ar : 0) * K + k0 + kc, okA ? 16 : 0);
            uint32_t sbb = (uint32_t)__cvta_generic_to_shared(Bd + row * MMA_PAD + kc);
            cp_async16(sbb, W + (size_t)row * K + k0 + kc, 16);
        }
        cp_commit();
    };

    const int NIT = K / 32;
    load_tile(0, 0);
    for (int it = 0; it < NIT; it++) {
        int cur = it & 1;
        if (it + 1 < NIT) { load_tile(it + 1, cur ^ 1); cp_wait<1>(); }
        else cp_wait<0>();
        __syncthreads();

        const float* Ac = Abuf + cur * MMA_STAGE_F;
        const float* Bc = Bbuf + cur * MMA_STAGE_F;
#pragma unroll
        for (int ks = 0; ks < 4; ks++) {
            int kb = ks * 8;
            uint32_t a[4][4];
#pragma unroll
            for (int mt = 0; mt < 4; mt++) {
                int mrow = wm + mt * 16 + gr;
                a[mt][0] = __float_as_uint(Ac[mrow * MMA_PAD + kb + gc]);
                a[mt][1] = __float_as_uint(Ac[(mrow + 8) * MMA_PAD + kb + gc]);
                a[mt][2] = __float_as_uint(Ac[mrow * MMA_PAD + kb + gc + 4]);
                a[mt][3] = __float_as_uint(Ac[(mrow + 8) * MMA_PAD + kb + gc + 4]);
            }
            uint32_t b[4][2];
#pragma unroll
            for (int nt = 0; nt < 4; nt++) {
                int ncol = wn + nt * 8 + gr;
                b[nt][0] = __float_as_uint(Bc[ncol * MMA_PAD + kb + gc]);
                b[nt][1] = __float_as_uint(Bc[ncol * MMA_PAD + kb + gc + 4]);
            }
#pragma unroll
            for (int mt = 0; mt < 4; mt++)
#pragma unroll
                for (int nt = 0; nt < 4; nt++)
                    mma_tf32(c[mt][nt], a[mt][0], a[mt][1], a[mt][2], a[mt][3],
                             b[nt][0], b[nt][1]);
        }
        __syncthreads();
    }

    float* sm_as = smemf;
    float* sm_ad = smemf + 512;

    int crow = lane >> 2, ccol = (lane & 3) * 2;
    float av[4][2], dv[4][2];
#pragma unroll
    for (int nt = 0; nt < 4; nt++)
#pragma unroll
        for (int j = 0; j < 2; j++) {
            int col = wn + nt * 8 + ccol + j;
            av[nt][j] = asrc[col];
            dv[nt][j] = adst[col];
        }

#pragma unroll
    for (int mt = 0; mt < 4; mt++) {
#pragma unroll
        for (int h = 0; h < 2; h++) {
            int lrow = wm + mt * 16 + crow + h * 8;
            int row = bm + lrow;
            float pas = 0.f, pad = 0.f;
            if (row < M) {
#pragma unroll
                for (int nt = 0; nt < 4; nt++) {
                    float v0 = c[mt][nt][h * 2];
                    float v1 = c[mt][nt][h * 2 + 1];
                    int col = wn + nt * 8 + ccol;
                    *(__nv_bfloat162*)(g_h16 + (size_t)row * D + col) =
                        __floats2bfloat162_rn(v0, v1);
                    pas += v0 * av[nt][0] + v1 * av[nt][1];
                    pad += v0 * dv[nt][0] + v1 * dv[nt][1];
                }
            }
            pas += __shfl_xor_sync(0xffffffff, pas, 1);
            pas += __shfl_xor_sync(0xffffffff, pas, 2);
            pad += __shfl_xor_sync(0xffffffff, pad, 1);
            pad += __shfl_xor_sync(0xffffffff, pad, 2);
            if ((lane & 3) == 0) {
                sm_as[lrow * 4 + wnw] = pas;
                sm_ad[lrow * 4 + wnw] = pad;
            }
        }
    }
    __syncthreads();
    if (tid < 128) {
        int row = bm + tid;
        if (row < M) {
            g_as[row] = sm_as[tid * 4] + sm_as[tid * 4 + 1] +
                        sm_as[tid * 4 + 2] + sm_as[tid * 4 + 3];
            g_ad[row] = sm_ad[tid * 4] + sm_ad[tid * 4 + 1] +
                        sm_ad[tid * 4 + 2] + sm_ad[tid * 4 + 3];
        }
    }
}

// ================= fp32 SGEMM lin1 with fused gather =================
__global__ __launch_bounds__(256) void k_sgemm_lin1(
    const int* __restrict__ x, const float* __restrict__ Bm,
    const float* __restrict__ bias)
{
    const int Nn = H3, K = H3;
    float* C = g_z1;

    __shared__ float As[8][128];
    __shared__ float Bs[8][128];

    int tid = threadIdx.x;
    int tx = tid & 15, ty = tid >> 4;
    int bm = blockIdx.y * 128, bn = blockIdx.x * 128;

    float acc[8][8];
#pragma unroll
    for (int i = 0; i < 8; i++)
#pragma unroll
        for (int j = 0; j < 8; j++) acc[i][j] = 0.f;

    int lr = tid >> 1;
    int lk = (tid & 1) * 4;

    for (int k0 = 0; k0 < K; k0 += 8) {
        int ar = bm + lr;
        int kidx = k0 + lk;
        int node = x[ar * 3 + (kidx >> 7)];
        float4 a4 = *(const float4*)(g_hn + (size_t)node * D + (kidx & 127));
        As[lk + 0][lr] = a4.x; As[lk + 1][lr] = a4.y;
        As[lk + 2][lr] = a4.z; As[lk + 3][lr] = a4.w;

        float4 b4 = make_float4(0.f, 0.f, 0.f, 0.f);
        int br = bn + lr;
        if (br < Nn) b4 = *(const float4*)(Bm + (size_t)br * K + kidx);
        Bs[lk + 0][lr] = b4.x; Bs[lk + 1][lr] = b4.y;
        Bs[lk + 2][lr] = b4.z; Bs[lk + 3][lr] = b4.w;
        __syncthreads();

#pragma unroll
        for (int k = 0; k < 8; k++) {
            float4 a0 = *(const float4*)&As[k][ty * 8];
            float4 a1 = *(const float4*)&As[k][ty * 8 + 4];
            float4 b0 = *(const float4*)&Bs[k][tx * 8];
            float4 b1 = *(const float4*)&Bs[k][tx * 8 + 4];
            float a[8] = {a0.x, a0.y, a0.z, a0.w, a1.x, a1.y, a1.z, a1.w};
            float b[8] = {b0.x, b0.y, b0.z, b0.w, b1.x, b1.y, b1.z, b1.w};
#pragma unroll
            for (int i = 0; i < 8; i++)
#pragma unroll
                for (int j = 0; j < 8; j++) acc[i][j] += a[i] * b[j];
        }
        __syncthreads();
    }

#pragma unroll
    for (int i = 0; i < 8; i++) {
        int row = bm + ty * 8 + i;
#pragma unroll
        for (int j = 0; j < 8; j++) {
            int col = bn + tx * 8 + j;
            if (col < Nn) C[(size_t)row * Nn + col] = acc[i][j] + bias[col];
        }
    }
}

// ================= fused LSE reduce + subtract (one block per row) ========
__global__ __launch_bounds__(256) void k_lse_sub(float* __restrict__ out) {
    int row = blockIdx.x;
    int tid = threadIdx.x;
    int lane = tid & 31, wid = tid >> 5;

    // per-block reduction of this row's 391 tile partials
    const float* pm = g_pmax + (size_t)row * NT_TILES;
    const float* ps = g_psum + (size_t)row * NT_TILES;
    float M = NEG_INF;
    for (int i = tid; i < NT_TILES; i += 256) M = fmaxf(M, pm[i]);
#pragma unroll
    for (int o = 16; o; o >>= 1) M = fmaxf(M, __shfl_xor_sync(0xffffffff, M, o));
    __shared__ float wsm[8], wss[8];
    __shared__ float s_lse;
    if (lane == 0) wsm[wid] = M;
    __syncthreads();
    if (wid == 0) {
        float m2 = (lane < 8) ? wsm[lane] : NEG_INF;
#pragma unroll
        for (int o = 4; o; o >>= 1) m2 = fmaxf(m2, __shfl_xor_sync(0xffffffff, m2, o));
        if (lane == 0) wsm[0] = m2;
    }
    __syncthreads();
    float Mg = wsm[0];

    float S = 0.f;
    for (int i = tid; i < NT_TILES; i += 256) S += ps[i] * __expf(pm[i] - Mg);
#pragma unroll
    for (int o = 16; o; o >>= 1) S += __shfl_xor_sync(0xffffffff, S, o);
    if (lane == 0) wss[wid] = S;
    __syncthreads();
    if (wid == 0) {
        float s2 = (lane < 8) ? wss[lane] : 0.f;
#pragma unroll
        for (int o = 4; o; o >>= 1) s2 += __shfl_xor_sync(0xffffffff, s2, o);
        if (lane == 0) s_lse = Mg + logf(s2);
    }
    __syncthreads();
    float l = s_lse;

    // subtract over this row (12500 float4)
    float4* p = (float4*)(out + (size_t)row * N_NODES);
    for (int i = tid; i < 12500; i += 256) {
        float4 v = p[i];
        v.x -= l; v.y -= l; v.z -= l; v.w -= l;
        p[i] = v;
    }
}

// ================= per-node attention aggregate (fused expsum) ============
__global__ void k_node_attagg() {
    int gt = blockIdx.x * blockDim.x + threadIdx.x;
    int node = gt >> 5, lane = gt & 31;
    if (node >= N_NODES) return;
    int beg = g_off[node], end = g_off[node + 1];
    float ad = g_ad[node];

    float m = NEG_INF;
    for (int i = beg + lane; i < end; i += 32) {
        float s = g_as[g_srcl[i]] + ad;
        float e = (s > 0.f) ? s : 0.2f * s;
        g_e[i] = e;
        m = fmaxf(m, e);
    }
#pragma unroll
    for (int o = 16; o; o >>= 1) m = fmaxf(m, __shfl_xor_sync(0xffffffff, m, o));
    __syncwarp();

    float4 acc = make_float4(0.f, 0.f, 0.f, 0.f);
    float den = 0.f;
    int coff = lane * 4;
    int i = beg;
    for (; i + 3 < end; i += 4) {
        float w0 = __expf(g_e[i] - m),     w1 = __expf(g_e[i + 1] - m);
        float w2 = __expf(g_e[i + 2] - m), w3 = __expf(g_e[i + 3] - m);
        den += (w0 + w1) + (w2 + w3);
        int s0 = g_srcl[i],     s1 = g_srcl[i + 1];
        int s2 = g_srcl[i + 2], s3 = g_srcl[i + 3];
        uint2 p0 = *(const uint2*)(g_h16 + (size_t)s0 * D + coff);
        uint2 p1 = *(const uint2*)(g_h16 + (size_t)s1 * D + coff);
        uint2 p2 = *(const uint2*)(g_h16 + (size_t)s2 * D + coff);
        uint2 p3 = *(const uint2*)(g_h16 + (size_t)s3 * D + coff);
        float2 a0 = __bfloat1622float2(*(__nv_bfloat162*)&p0.x);
        float2 b0 = __bfloat1622float2(*(__nv_bfloat162*)&p0.y);
        float2 a1 = __bfloat1622float2(*(__nv_bfloat162*)&p1.x);
        float2 b1 = __bfloat1622float2(*(__nv_bfloat162*)&p1.y);
        float2 a2 = __bfloat1622float2(*(__nv_bfloat162*)&p2.x);
        float2 b2 = __bfloat1622float2(*(__nv_bfloat162*)&p2.y);
        float2 a3 = __bfloat1622float2(*(__nv_bfloat162*)&p3.x);
        float2 b3 = __bfloat1622float2(*(__nv_bfloat162*)&p3.y);
        acc.x += w0 * a0.x + w1 * a1.x + w2 * a2.x + w3 * a3.x;
        acc.y += w0 * a0.y + w1 * a1.y + w2 * a2.y + w3 * a3.y;
        acc.z += w0 * b0.x + w1 * b1.x + w2 * b2.x + w3 * b3.x;
        acc.w += w0 * b0.y + w1 * b1.y + w2 * b2.y + w3 * b3.y;
    }
    for (; i < end; i++) {
        float w = __expf(g_e[i] - m);
        den += w;
        int s = g_srcl[i];
        uint2 p = *(const uint2*)(g_h16 + (size_t)s * D + coff);
        float2 a = __bfloat1622float2(*(__nv_bfloat162*)&p.x);
        float2 b = __bfloat1622float2(*(__nv_bfloat162*)&p.y);
        acc.x += w * a.x; acc.y += w * a.y;
        acc.z += w * b.x; acc.w += w * b.y;
    }
    float inv = 1.f / den;
    acc.x *= inv; acc.y *= inv; acc.z *= inv; acc.w *= inv;
    *(float4*)(g_agg + (size_t)node * D + coff) = acc;
}

// ================= GraphNorm =================
#define RPB 64
__global__ void k_colstats(int layer) {
    int col = threadIdx.x;
    int r0 = blockIdx.x * RPB;
    int r1 = min(r0 + RPB, N_NODES);
    float s = 0.f, s2 = 0.f;
    for (int r = r0; r < r1; r++) {
        float a = g_agg[(size_t)r * D + col];
        s += a; s2 += a * a;
    }
    atomicAdd(&g_musum2[layer * D + col], s);
    atomicAdd(&g_varsum2[layer * D + col], s2);
}
__global__ void k_normalize(const float* __restrict__ bb, const float* __restrict__ gw,
                            const float* __restrict__ gb, const float* __restrict__ ms,
                            int layer) {
    int idx = blockIdx.x * blockDim.x + threadIdx.x;
    if (idx >= N_NODES * D) return;
    int d = idx & (D - 1);
    float S1 = g_musum2[layer * D + d] * (1.f / N_NODES);
    float S2 = g_varsum2[layer * D + d] * (1.f / N_NODES);
    float bv = bb[d];
    float mu = S1 + bv;
    float cc = bv - mu * ms[d];
    float var = S2 + 2.f * cc * S1 + cc * cc;
    float istd = rsqrtf(var + EPSV);
    float t = g_agg[idx] + cc;
    float v = t * istd * gw[d] + gb[d];
    g_hn[idx] = v > 0.f ? v : 0.f;
}

// ================= head BN =================
__global__ void k_bn_relu(const float* __restrict__ bw, const float* __restrict__ bb) {
    int c = blockIdx.x;
    int t = threadIdx.x;
    __shared__ float sm[256], ss[256];
    float s = 0.f, s2 = 0.f;
    for (int r = t; r < BQ; r += 256) {
        float v = g_z1[r * H3 + c];
        s += v; s2 += v * v;
    }
    sm[t] = s; ss[t] = s2;
    __syncthreads();
    for (int o = 128; o; o >>= 1) {
        if (t < o) { sm[t] += sm[t + o]; ss[t] += ss[t + o]; }
        __syncthreads();
    }
    float mu = sm[0] * (1.f / BQ);
    float var = ss[0] * (1.f / BQ) - mu * mu;
    float istd = rsqrtf(var + EPSV);
    float w = bw[c], bias = bb[c];
    for (int r = t; r < BQ; r += 256) {
        float v = (g_z1[r * H3 + c] - mu) * istd * w + bias;
        g_z16[r * H3 + c] = __float2bfloat16(v > 0.f ? v : 0.f);
    }
}

// ================= host driver =================
extern "C" void kernel_launch(void* const* d_in, const int* in_sizes, int n_in,
                              void* d_out, int out_size)
{
    const int*   x       = (const int*)  d_in[0];
    const int*   ei      = (const int*)  d_in[1];
    const float* emb     = (const float*)d_in[2];
    const float* W1      = (const float*)d_in[3];
    const float* asrc1   = (const float*)d_in[4];
    const float* adst1   = (const float*)d_in[5];
    const float* b1      = (const float*)d_in[6];
    const float* gn1w    = (const float*)d_in[7];
    const float* gn1b    = (const float*)d_in[8];
    const float* gn1ms   = (const float*)d_in[9];
    const float* W2      = (const float*)d_in[10];
    const float* asrc2   = (const float*)d_in[11];
    const float* adst2   = (const float*)d_in[12];
    const float* b2      = (const float*)d_in[13];
    const float* gn2w    = (const float*)d_in[14];
    const float* gn2b    = (const float*)d_in[15];
    const float* gn2ms   = (const float*)d_in[16];
    const float* lin1W   = (const float*)d_in[17];
    const float* lin1b   = (const float*)d_in[18];
    const float* bnw     = (const float*)d_in[19];
    const float* bnb     = (const float*)d_in[20];
    const float* lin2W   = (const float*)d_in[21];
    const float* lin2b   = (const float*)d_in[22];
    float* out = (float*)d_out;

    // one-time resource init (first call is the uncaptured correctness run)
    static cudaStream_t s_b = nullptr;
    static cudaEvent_t ev_fork = nullptr, ev_join = nullptr;
    if (s_b == nullptr) {
        cudaStreamCreateWithFlags(&s_b, cudaStreamNonBlocking);
        cudaEventCreateWithFlags(&ev_fork, cudaEventDisableTiming);
        cudaEventCreateWithFlags(&ev_join, cudaEventDisableTiming);
        cudaFuncSetAttribute(k_mma_lin2, cudaFuncAttributeMaxDynamicSharedMemorySize, LIN2_SMEM_B);
        cudaFuncSetAttribute(k_mma_feat, cudaFuncAttributeMaxDynamicSharedMemorySize, FEAT_SMEM_B);
    }

    dim3 gf(1, NT_TILES);

    // ---- fork: stream B does cvt_w + feat layer-1; main stream does CSR ----
    cudaEventRecord(ev_fork, 0);
    cudaStreamWaitEvent(s_b, ev_fork, 0);

    k_cvt_w<<<(N_NODES * H3 / 4 + 255) / 256, 256, 0, s_b>>>(lin2W);
    k_mma_feat<<<gf, 256, FEAT_SMEM_B, s_b>>>(emb, W1, asrc1, adst1, 0);
    cudaEventRecord(ev_join, s_b);

    k_zero_deg<<<(N_NODES + 255) / 256, 256>>>();
    k_count<<<(ET + 255) / 256, 256>>>(ei);
    k_bsums<<<NB_SCAN, 256>>>();
    k_scan2<<<1, 256>>>();
    k_addback<<<NB_SCAN, 256>>>();
    k_fill<<<(ET + 255) / 256, 256>>>(ei);

    cudaStreamWaitEvent(0, ev_join, 0);
    // ---- join ----

    // --- layer 1 rest ---
    k_node_attagg<<<(N_NODES * 32 + 255) / 256, 256>>>();
    k_colstats<<<(N_NODES + RPB - 1) / RPB, D>>>(0);
    k_normalize<<<(N_NODES * D + 255) / 256, 256>>>(b1, gn1w, gn1b, gn1ms, 0);

    // --- layer 2 ---
    k_mma_feat<<<gf, 256, FEAT_SMEM_B>>>(nullptr, W2, asrc2, adst2, 1);
    k_node_attagg<<<(N_NODES * 32 + 255) / 256, 256>>>();
    k_colstats<<<(N_NODES + RPB - 1) / RPB, D>>>(1);
    k_normalize<<<(N_NODES * D + 255) / 256, 256>>>(b2, gn2w, gn2b, gn2ms, 1);

    // --- head ---
    dim3 gz1((H3 + 127) / 128, BQ / 128);
    k_sgemm_lin1<<<gz1, 256>>>(x, lin1W, lin1b);
    k_bn_relu<<<H3, 256>>>(bnw, bnb);
    dim3 gz2(NT_TILES, BQ / 128);
    k_mma_lin2<<<gz2, 256, LIN2_SMEM_B>>>(lin2b, out);
    k_lse_sub<<<BQ, 256>>>(out);
}